// round 1
// baseline (speedup 1.0000x reference)
#include <cuda_runtime.h>
#include <math.h>

#define BATCH 16
#define SEQL  2048
#define BL    (BATCH*SEQL)      // 32768
#define DM    128
#define DI    256
#define DX    384
#define NH    4
#define HD    64
#define DS    64
#define CH    64
#define NC    (SEQL/CH)         // 32
#define NPROJ 644

// ---------------- scratch (device globals; no allocations allowed) ----------
__device__ float g_z[2][BL*DI];          // gate z
__device__ float g_xbc0[2][BL*DX];       // pre-conv xBC
__device__ float g_xbc[2][BL*DX];        // post conv+silu xBC
__device__ float g_dt[2][BL*NH];         // softplus(dt)
__device__ float g_st[2][BATCH*NC*NH*HD*DS]; // chunk states -> prev states (in-place)
__device__ float g_yd[2][BL*DI];         // diagonal-block Y
__device__ float g_cd[2][BATCH*NH*NC];   // chunk decay

__device__ __forceinline__ float softplusf(float x){ return x > 20.f ? x : log1pf(expf(x)); }
__device__ __forceinline__ float siluf(float x){ return x / (1.f + expf(-x)); }

// ---------------- K1: in_proj GEMM  out = x @ Wi^T  (with time flip for dir=1)
__global__ void k_inproj(const float* __restrict__ x,
                         const float* __restrict__ Wi_f, const float* __restrict__ Wi_b,
                         const float* __restrict__ db_f, const float* __restrict__ db_b)
{
    int dir = blockIdx.z;
    const float* Wi = dir ? Wi_b : Wi_f;
    const float* db = dir ? db_b : db_f;
    __shared__ float sX[64][65];
    __shared__ float sW[64][65];
    int tid = threadIdx.x;
    int m0 = blockIdx.x * 64;
    int n0 = blockIdx.y * 64;
    int tr = tid >> 4, tc = tid & 15;
    float acc[4][4] = {};
    for (int kk = 0; kk < 128; kk += 64) {
        for (int i = tid; i < 4096; i += 256) {
            int r = i >> 6, k = i & 63;
            int m = m0 + r;
            int b = m >> 11, t = m & 2047;
            int xr = dir ? ((b << 11) + (2047 - t)) : m;
            sX[r][k] = x[xr * 128 + kk + k];
            int j = n0 + r;
            sW[r][k] = (j < NPROJ) ? Wi[j * 128 + kk + k] : 0.f;
        }
        __syncthreads();
        for (int k = 0; k < 64; k++) {
            float a[4], bb[4];
            #pragma unroll
            for (int i = 0; i < 4; i++) a[i] = sX[tr*4+i][k];
            #pragma unroll
            for (int j = 0; j < 4; j++) bb[j] = sW[tc*4+j][k];
            #pragma unroll
            for (int i = 0; i < 4; i++)
                #pragma unroll
                for (int j = 0; j < 4; j++) acc[i][j] += a[i] * bb[j];
        }
        __syncthreads();
    }
    #pragma unroll
    for (int i = 0; i < 4; i++) {
        int m = m0 + tr*4 + i;
        #pragma unroll
        for (int j = 0; j < 4; j++) {
            int c = n0 + tc*4 + j;
            if (c >= NPROJ) continue;
            float v = acc[i][j];
            if (c < DI)            g_z[dir][m*DI + c] = v;
            else if (c < DI + DX)  g_xbc0[dir][m*DX + (c - DI)] = v;
            else                   g_dt[dir][m*NH + (c - DI - DX)] = softplusf(v + db[c - DI - DX]);
        }
    }
}

// ---------------- K2: causal depthwise conv(4) + bias + silu -----------------
__global__ void k_conv(const float* __restrict__ cw_f, const float* __restrict__ cb_f,
                       const float* __restrict__ cw_b, const float* __restrict__ cb_b)
{
    int dir = blockIdx.y;
    const float* cw = dir ? cw_b : cw_f;
    const float* cb = dir ? cb_b : cb_f;
    int idx = blockIdx.x * 256 + threadIdx.x;
    if (idx >= BL * DX) return;
    int m = idx / DX, j = idx - m * DX;
    int t = m & 2047;
    float acc = cb[j];
    #pragma unroll
    for (int k = 0; k < 4; k++) {
        int tt = t - 3 + k;
        if (tt >= 0) acc += g_xbc0[dir][(m - 3 + k) * DX + j] * cw[j*4 + k];
    }
    g_xbc[dir][idx] = siluf(acc);
}

// ---------------- K3: per-chunk diagonal block + chunk state ------------------
// smem floats: sB 4160 | sC 4160 | sX 16448 | sCB 4160 | sW 4160 | sdt 256 | sAcs 256 | sdec 64
#define SM3_FLOATS 33664
__global__ void k_chunk(const float* __restrict__ Al_f, const float* __restrict__ Al_b)
{
    extern __shared__ float sm[];
    float (*sB)[65]   = (float(*)[65])(sm);
    float (*sC)[65]   = (float(*)[65])(sm + 4160);
    float (*sX)[257]  = (float(*)[257])(sm + 8320);
    float (*sCB)[65]  = (float(*)[65])(sm + 24768);
    float (*sW)[65]   = (float(*)[65])(sm + 28928);
    float (*sdt)[4]   = (float(*)[4])(sm + 33088);
    float (*sAcs)[64] = (float(*)[64])(sm + 33344);
    float *sdec       = sm + 33600;

    int c = blockIdx.x, b = blockIdx.y, dir = blockIdx.z;
    const float* Alog = dir ? Al_b : Al_f;
    int tid = threadIdx.x;
    int base = b * SEQL + c * CH;

    for (int i = tid; i < 64*64; i += 256) {
        int l = i >> 6, n = i & 63;
        sB[l][n] = g_xbc[dir][(base + l)*DX + DI + n];
        sC[l][n] = g_xbc[dir][(base + l)*DX + DI + DS + n];
    }
    for (int i = tid; i < 64*4; i += 256) {
        int l = i >> 2, h = i & 3;
        sdt[l][h] = g_dt[dir][(base + l)*NH + h];
    }
    __syncthreads();
    for (int i = tid; i < 64*256; i += 256) {
        int l = i >> 8, q = i & 255, h = q >> 6;
        sX[l][q] = g_xbc[dir][(base + l)*DX + q] * sdt[l][h];
    }
    if (tid < 4) {
        float A = -expf(Alog[tid]);
        float run = 0.f;
        for (int l = 0; l < 64; l++) { run += sdt[l][tid] * A; sAcs[tid][l] = run; }
    }
    __syncthreads();
    // CB[l][s] = C[l]·B[s]  (lower triangle only)
    for (int i = tid; i < 4096; i += 256) {
        int l = i >> 6, s = i & 63;
        float acc = 0.f;
        if (s <= l)
            for (int n = 0; n < 64; n++) acc += sC[l][n] * sB[s][n];
        sCB[l][s] = acc;
    }
    __syncthreads();
    for (int h = 0; h < NH; h++) {
        for (int i = tid; i < 4096; i += 256) {
            int l = i >> 6, s = i & 63;
            sW[l][s] = (s <= l) ? sCB[l][s] * expf(sAcs[h][l] - sAcs[h][s]) : 0.f;
        }
        if (tid < 64) sdec[tid] = expf(sAcs[h][63] - sAcs[h][tid]);
        __syncthreads();
        // Y_diag = (CB .* L) @ Xdt
        for (int i = tid; i < 4096; i += 256) {
            int l = i >> 6, p = i & 63;
            float acc = 0.f;
            for (int s = 0; s <= l; s++) acc += sW[l][s] * sX[s][h*64 + p];
            g_yd[dir][(base + l)*DI + h*64 + p] = acc;
        }
        // st[p][n] = sum_l dec[l] * Xdt[l][p] * B[l][n]
        for (int i = tid; i < 4096; i += 256) {
            int p = i >> 6, n = i & 63;
            float acc = 0.f;
            for (int l = 0; l < 64; l++) acc += (sdec[l] * sX[l][h*64 + p]) * sB[l][n];
            g_st[dir][((b*NC + c)*NH + h)*4096 + p*64 + n] = acc;
        }
        if (tid == 0) g_cd[dir][(b*NH + h)*NC + c] = expf(sAcs[h][63]);
        __syncthreads();
    }
}

// ---------------- K4: sequential inter-chunk scan (in-place prev) -------------
__global__ void k_scan()
{
    int h = blockIdx.x, b = blockIdx.y, dir = blockIdx.z;
    int tid = threadIdx.x;
    float carry[16];
    #pragma unroll
    for (int k = 0; k < 16; k++) carry[k] = 0.f;
    for (int c = 0; c < NC; c++) {
        float cdv = g_cd[dir][(b*NH + h)*NC + c];
        int sbase = ((b*NC + c)*NH + h) * 4096;
        #pragma unroll
        for (int k = 0; k < 16; k++) {
            int e = tid + k*256;
            float tmp = g_st[dir][sbase + e];
            g_st[dir][sbase + e] = carry[k];          // prev state entering chunk c
            carry[k] = carry[k] * cdv + tmp;
        }
    }
}

// ---------------- K5: off-diag Y + D + gate + RMSnorm + out_proj + combine ----
// smem floats: sPrev 16640 | sC 4160 | sY 16448 | sdt 256 | sAcs 256 | sScale 64
#define SM5_FLOATS 37824
__global__ void k_out(const float* __restrict__ Al_f, const float* __restrict__ Al_b,
                      const float* __restrict__ D_f,  const float* __restrict__ D_b,
                      const float* __restrict__ nw_f, const float* __restrict__ nw_b,
                      const float* __restrict__ Wo_f, const float* __restrict__ Wo_b,
                      float* __restrict__ out)
{
    extern __shared__ float sm[];
    float (*sPrev)[65] = (float(*)[65])(sm);          // [h*64+p][n]
    float (*sC)[65]    = (float(*)[65])(sm + 16640);
    float (*sY)[257]   = (float(*)[257])(sm + 20800);
    float (*sdt)[4]    = (float(*)[4])(sm + 37248);
    float (*sAcs)[64]  = (float(*)[64])(sm + 37504);
    float *sScale      = sm + 37760;

    int c = blockIdx.x, b = blockIdx.y, dir = blockIdx.z;
    const float* Alog = dir ? Al_b : Al_f;
    const float* Dp   = dir ? D_b  : D_f;
    const float* nw   = dir ? nw_b : nw_f;
    const float* Wo   = dir ? Wo_b : Wo_f;
    int tid = threadIdx.x;
    int base = b * SEQL + c * CH;

    for (int i = tid; i < 64*64; i += 256) {
        int l = i >> 6, n = i & 63;
        sC[l][n] = g_xbc[dir][(base + l)*DX + DI + DS + n];
    }
    {
        int pbase = (b*NC + c)*NH * 4096;
        for (int i = tid; i < NH*64*64; i += 256) {
            int hp = i >> 6, n = i & 63;
            sPrev[hp][n] = g_st[dir][pbase + i];
        }
    }
    for (int i = tid; i < 256; i += 256) {
        int l = i >> 2, h = i & 3;
        sdt[l][h] = g_dt[dir][(base + l)*NH + h];
    }
    __syncthreads();
    if (tid < 4) {
        float A = -expf(Alog[tid]);
        float run = 0.f;
        for (int l = 0; l < 64; l++) { run += sdt[l][tid] * A; sAcs[tid][l] = run; }
    }
    __syncthreads();
    // Y = Ydiag + exp(Acs)*(C @ prev^T) + D*xs ; gate with silu(z)
    for (int i = tid; i < 64*256; i += 256) {
        int l = i >> 8, q = i & 255, h = q >> 6, p = q & 63;
        float acc = 0.f;
        for (int n = 0; n < 64; n++) acc += sC[l][n] * sPrev[h*64 + p][n];
        float yv = g_yd[dir][(base + l)*DI + q]
                 + expf(sAcs[h][l]) * acc
                 + Dp[h] * g_xbc[dir][(base + l)*DX + q];
        float z = g_z[dir][(base + l)*DI + q];
        sY[l][q] = yv * siluf(z);
    }
    __syncthreads();
    if (tid < 64) {
        float s = 0.f;
        for (int q = 0; q < 256; q++) { float v = sY[tid][q]; s += v*v; }
        sScale[tid] = rsqrtf(s / 256.f + 1e-5f);
    }
    __syncthreads();
    for (int i = tid; i < 64*256; i += 256) {
        int l = i >> 8, q = i & 255;
        sY[l][q] *= sScale[l] * nw[q];
    }
    __syncthreads();
    // out_proj: [64,256] @ Wo^T[256,128], combine both directions via atomicAdd
    for (int i = tid; i < 64*128; i += 256) {
        int l = i >> 7, k = i & 127;
        float acc = 0.f;
        for (int j = 0; j < 256; j++) acc += sY[l][j] * Wo[k*256 + j];
        int t = c*CH + l;
        int tout = dir ? (SEQL - 1 - t) : t;
        atomicAdd(&out[(b*SEQL + tout)*DM + k], acc);
    }
}

// ---------------- K0: zero output --------------------------------------------
__global__ void k_zero(float* out, int n)
{
    int i = blockIdx.x * 256 + threadIdx.x;
    if (i < n) out[i] = 0.f;
}

extern "C" void kernel_launch(void* const* d_in, const int* in_sizes, int n_in,
                              void* d_out, int out_size)
{
    const float* x    = (const float*)d_in[0];
    const float* Wi_f = (const float*)d_in[1];
    const float* cw_f = (const float*)d_in[2];
    const float* cb_f = (const float*)d_in[3];
    const float* db_f = (const float*)d_in[4];
    const float* Al_f = (const float*)d_in[5];
    const float* D_f  = (const float*)d_in[6];
    const float* nw_f = (const float*)d_in[7];
    const float* Wo_f = (const float*)d_in[8];
    const float* Wi_b = (const float*)d_in[9];
    const float* cw_b = (const float*)d_in[10];
    const float* cb_b = (const float*)d_in[11];
    const float* db_b = (const float*)d_in[12];
    const float* Al_b = (const float*)d_in[13];
    const float* D_b  = (const float*)d_in[14];
    const float* nw_b = (const float*)d_in[15];
    const float* Wo_b = (const float*)d_in[16];
    float* out = (float*)d_out;

    cudaFuncSetAttribute(k_chunk, cudaFuncAttributeMaxDynamicSharedMemorySize, SM3_FLOATS * 4);
    cudaFuncSetAttribute(k_out,   cudaFuncAttributeMaxDynamicSharedMemorySize, SM5_FLOATS * 4);

    k_zero<<<(out_size + 255)/256, 256>>>(out, out_size);

    dim3 g1(BL/64, (NPROJ + 63)/64, 2);
    k_inproj<<<g1, 256>>>(x, Wi_f, Wi_b, db_f, db_b);

    dim3 g2((BL*DX + 255)/256, 2);
    k_conv<<<g2, 256>>>(cw_f, cb_f, cw_b, cb_b);

    dim3 g3(NC, BATCH, 2);
    k_chunk<<<g3, 256, SM3_FLOATS * 4>>>(Al_f, Al_b);

    dim3 g4(NH, BATCH, 2);
    k_scan<<<g4, 256>>>();

    k_out<<<g3, 256, SM5_FLOATS * 4>>>(Al_f, Al_b, D_f, D_b, nw_f, nw_b, Wo_f, Wo_b, out);
}

// round 2
// speedup vs baseline: 6.1269x; 6.1269x over previous
#include <cuda_runtime.h>
#include <math.h>

#define BATCH 16
#define SEQL  2048
#define BL    (BATCH*SEQL)      // 32768
#define DM    128
#define DI    256
#define DX    384
#define NH    4
#define HD    64
#define DS    64
#define CH    64
#define NC    32
#define NPROJ 644

// ---------------- scratch ----------------------------------------------------
__device__ float g_z[2][BL*DI];
__device__ float g_xbc0[2][BL*DX];
__device__ float g_xbc[2][BL*DX];
__device__ float g_dt[2][BL*NH];
__device__ float g_st[2][BATCH*NC*NH*HD*DS];   // per h: [n][p] (transposed)
__device__ float g_yd[2][BL*DI];
__device__ float g_cd[2][BATCH*NH*NC];

__device__ __forceinline__ float softplusf(float x){ return x > 20.f ? x : log1pf(__expf(x)); }
__device__ __forceinline__ float siluf(float x){ return x / (1.f + __expf(-x)); }
__device__ __forceinline__ float dot4(float4 a, float4 b){
    return a.x*b.x + a.y*b.y + a.z*b.z + a.w*b.w;
}
__device__ __forceinline__ void fma4(float4& acc, float s, float4 v){
    acc.x += s*v.x; acc.y += s*v.y; acc.z += s*v.z; acc.w += s*v.w;
}

// ================= K1: in_proj GEMM (x @ Wi^T), time-flip for dir=1 ==========
// tile 128m x 64n, K=128 in two 64-chunks. 256 threads, per-thread 8m x 4n.
#define IP_SMEM ((128*68 + 64*68)*4)
__global__ __launch_bounds__(256) void k_inproj(
    const float* __restrict__ x,
    const float* __restrict__ Wi_f, const float* __restrict__ Wi_b,
    const float* __restrict__ db_f, const float* __restrict__ db_b)
{
    extern __shared__ float sm[];
    float (*sX)[68] = (float(*)[68])sm;            // [128][68]
    float (*sW)[68] = (float(*)[68])(sm + 128*68); // [64][68]
    int dir = blockIdx.z;
    const float* Wi = dir ? Wi_b : Wi_f;
    const float* db = dir ? db_b : db_f;
    int tid = threadIdx.x;
    int m0 = blockIdx.x * 128;
    int n0 = blockIdx.y * 64;
    int tm = tid & 15, tn = tid >> 4;
    float acc[8][4] = {};

    for (int kk = 0; kk < 2; kk++) {
        #pragma unroll
        for (int it = 0; it < 8; it++) {
            int q = tid + it*256;
            int row = q >> 4, kq = (q & 15) * 4;
            int m = m0 + row;
            int xr = dir ? ((m & ~2047) + 2047 - (m & 2047)) : m;
            *(float4*)&sX[row][kq] = *(const float4*)&x[xr*128 + kk*64 + kq];
        }
        #pragma unroll
        for (int it = 0; it < 4; it++) {
            int q = tid + it*256;
            int row = q >> 4, kq = (q & 15) * 4;
            int n = n0 + row;
            float4 v = make_float4(0.f,0.f,0.f,0.f);
            if (n < NPROJ) v = *(const float4*)&Wi[n*128 + kk*64 + kq];
            *(float4*)&sW[row][kq] = v;
        }
        __syncthreads();
        #pragma unroll
        for (int k4 = 0; k4 < 16; k4++) {
            float4 b4[4];
            #pragma unroll
            for (int j = 0; j < 4; j++) b4[j] = *(float4*)&sW[tn*4 + j][k4*4];
            #pragma unroll
            for (int i = 0; i < 8; i++) {
                float4 a = *(float4*)&sX[tm + 16*i][k4*4];
                #pragma unroll
                for (int j = 0; j < 4; j++) acc[i][j] += dot4(a, b4[j]);
            }
        }
        __syncthreads();
    }
    int nb = n0 + tn*4;
    #pragma unroll
    for (int i = 0; i < 8; i++) {
        int m = m0 + tm + 16*i;
        float4 v = make_float4(acc[i][0], acc[i][1], acc[i][2], acc[i][3]);
        if (nb < DI) {
            *(float4*)&g_z[dir][m*DI + nb] = v;
        } else if (nb < DI + DX) {
            *(float4*)&g_xbc0[dir][m*DX + (nb - DI)] = v;
        } else if (nb == DI + DX) {
            g_dt[dir][m*NH + 0] = softplusf(v.x + db[0]);
            g_dt[dir][m*NH + 1] = softplusf(v.y + db[1]);
            g_dt[dir][m*NH + 2] = softplusf(v.z + db[2]);
            g_dt[dir][m*NH + 3] = softplusf(v.w + db[3]);
        }
    }
}

// ================= K2: causal depthwise conv(4) + bias + silu (float4) =======
__global__ void k_conv(const float* __restrict__ cw_f, const float* __restrict__ cb_f,
                       const float* __restrict__ cw_b, const float* __restrict__ cb_b)
{
    int dir = blockIdx.y;
    const float* cw = dir ? cw_b : cw_f;
    const float* cb = dir ? cb_b : cb_f;
    int idx = blockIdx.x * 256 + threadIdx.x;   // quad index
    if (idx >= BL * DX / 4) return;
    int m = idx / (DX/4);
    int j = (idx - m * (DX/4)) * 4;
    int t = m & 2047;
    float4 acc = *(const float4*)&cb[j];
    float w[4][4];
    #pragma unroll
    for (int c = 0; c < 4; c++) {
        float4 wv = *(const float4*)&cw[(j + c) * 4];
        w[c][0] = wv.x; w[c][1] = wv.y; w[c][2] = wv.z; w[c][3] = wv.w;
    }
    #pragma unroll
    for (int k = 0; k < 4; k++) {
        int tt = t - 3 + k;
        if (tt >= 0) {
            float4 v = *(const float4*)&g_xbc0[dir][(m - 3 + k)*DX + j];
            acc.x += v.x * w[0][k];
            acc.y += v.y * w[1][k];
            acc.z += v.z * w[2][k];
            acc.w += v.w * w[3][k];
        }
    }
    acc.x = siluf(acc.x); acc.y = siluf(acc.y); acc.z = siluf(acc.z); acc.w = siluf(acc.w);
    *(float4*)&g_xbc[dir][m*DX + j] = acc;
}

// ================= K3: per-chunk diagonal block + chunk state ================
// dyn smem floats: sB[64][68] | sW[64][68] (first holds C) | sX[64][260] |
//                  sdt 256 | sAcs 256 | sdec 64   => 25920 floats
#define CH_SMEM (25920*4)
__global__ __launch_bounds__(256) void k_chunk(const float* __restrict__ Al_f,
                                               const float* __restrict__ Al_b)
{
    extern __shared__ float sm[];
    float (*sB)[68]   = (float(*)[68])sm;
    float (*sW)[68]   = (float(*)[68])(sm + 64*68);           // C, then W per head
    float (*sX)[260]  = (float(*)[260])(sm + 2*64*68);
    float (*sdt)[4]   = (float(*)[4])(sm + 2*64*68 + 64*260);
    float (*sAcs)[64] = (float(*)[64])(sm + 2*64*68 + 64*260 + 256);
    float *sdec       = sm + 2*64*68 + 64*260 + 512;

    int c = blockIdx.x, b = blockIdx.y, dir = blockIdx.z;
    const float* gx = g_xbc[dir];
    int tid = threadIdx.x;
    int base = b*SEQL + c*CH;

    { int l = tid >> 2, h = tid & 3; sdt[l][h] = g_dt[dir][base*NH + tid]; }
    #pragma unroll
    for (int it = 0; it < 4; it++) {
        int q = tid + it*256;
        int row = q >> 4, nq = (q & 15) * 4;
        *(float4*)&sB[row][nq] = *(const float4*)&gx[(base+row)*DX + DI + nq];
        *(float4*)&sW[row][nq] = *(const float4*)&gx[(base+row)*DX + DI + DS + nq]; // C
    }
    __syncthreads();
    #pragma unroll
    for (int it = 0; it < 16; it++) {
        int q = tid + it*256;
        int row = q >> 6, qq = (q & 63) * 4;
        float4 v = *(const float4*)&gx[(base+row)*DX + qq];
        float dtv = sdt[row][qq >> 6];
        v.x *= dtv; v.y *= dtv; v.z *= dtv; v.w *= dtv;
        *(float4*)&sX[row][qq] = v;
    }
    if (tid < 4) {
        float A = -__expf((dir ? Al_b : Al_f)[tid]);
        float run = 0.f;
        for (int l = 0; l < 64; l++) { run += sdt[l][tid] * A; sAcs[tid][l] = run; }
    }
    __syncthreads();

    // CB tile (4l x 4s) into registers; sW currently holds C
    int ts = tid & 15, tl = tid >> 4;
    float cb[4][4] = {};
    if (ts <= tl) {
        #pragma unroll
        for (int nq = 0; nq < 16; nq++) {
            float4 a4[4], b4[4];
            #pragma unroll
            for (int i = 0; i < 4; i++) a4[i] = *(float4*)&sW[tl*4 + i][nq*4];
            #pragma unroll
            for (int j = 0; j < 4; j++) b4[j] = *(float4*)&sB[ts*4 + j][nq*4];
            #pragma unroll
            for (int i = 0; i < 4; i++)
                #pragma unroll
                for (int j = 0; j < 4; j++) cb[i][j] += dot4(a4[i], b4[j]);
        }
    }
    __syncthreads();   // all C reads done; sW becomes the L-masked matrix

    int sbase = (b*NC + c)*NH*4096;
    for (int h = 0; h < NH; h++) {
        #pragma unroll
        for (int i = 0; i < 4; i++) {
            int l = tl*4 + i;
            float al = sAcs[h][l];
            float4 w;
            w.x = (ts*4+0 <= l) ? cb[i][0] * __expf(al - sAcs[h][ts*4+0]) : 0.f;
            w.y = (ts*4+1 <= l) ? cb[i][1] * __expf(al - sAcs[h][ts*4+1]) : 0.f;
            w.z = (ts*4+2 <= l) ? cb[i][2] * __expf(al - sAcs[h][ts*4+2]) : 0.f;
            w.w = (ts*4+3 <= l) ? cb[i][3] * __expf(al - sAcs[h][ts*4+3]) : 0.f;
            *(float4*)&sW[l][ts*4] = w;
        }
        if (tid < 64) sdec[tid] = __expf(sAcs[h][63] - sAcs[h][tid]);
        __syncthreads();

        // Y_diag: (CB .* L) @ Xdt   thread: 4l x 4p
        {
            float4 acc[4] = {};
            for (int sq = 0; sq <= tl; sq++) {
                float4 x0 = *(float4*)&sX[sq*4+0][h*64 + ts*4];
                float4 x1 = *(float4*)&sX[sq*4+1][h*64 + ts*4];
                float4 x2 = *(float4*)&sX[sq*4+2][h*64 + ts*4];
                float4 x3 = *(float4*)&sX[sq*4+3][h*64 + ts*4];
                #pragma unroll
                for (int i = 0; i < 4; i++) {
                    float4 w4 = *(float4*)&sW[tl*4 + i][sq*4];
                    fma4(acc[i], w4.x, x0);
                    fma4(acc[i], w4.y, x1);
                    fma4(acc[i], w4.z, x2);
                    fma4(acc[i], w4.w, x3);
                }
            }
            #pragma unroll
            for (int i = 0; i < 4; i++)
                *(float4*)&g_yd[dir][(base + tl*4 + i)*DI + h*64 + ts*4] = acc[i];
        }
        // chunk state st[n][p] (transposed store)  thread: 4p(tl) x 4n(ts)
        {
            float st[4][4] = {};   // [p][n]
            for (int l = 0; l < 64; l++) {
                float d = sdec[l];
                float4 x4 = *(float4*)&sX[l][h*64 + tl*4];
                float4 b4 = *(float4*)&sB[l][ts*4];
                x4.x *= d; x4.y *= d; x4.z *= d; x4.w *= d;
                st[0][0] += x4.x*b4.x; st[0][1] += x4.x*b4.y; st[0][2] += x4.x*b4.z; st[0][3] += x4.x*b4.w;
                st[1][0] += x4.y*b4.x; st[1][1] += x4.y*b4.y; st[1][2] += x4.y*b4.z; st[1][3] += x4.y*b4.w;
                st[2][0] += x4.z*b4.x; st[2][1] += x4.z*b4.y; st[2][2] += x4.z*b4.z; st[2][3] += x4.z*b4.w;
                st[3][0] += x4.w*b4.x; st[3][1] += x4.w*b4.y; st[3][2] += x4.w*b4.z; st[3][3] += x4.w*b4.w;
            }
            #pragma unroll
            for (int j = 0; j < 4; j++) {
                float4 v = make_float4(st[0][j], st[1][j], st[2][j], st[3][j]);
                *(float4*)&g_st[dir][sbase + h*4096 + (ts*4 + j)*64 + tl*4] = v;
            }
        }
        if (tid == 0) g_cd[dir][(b*NH + h)*NC + c] = __expf(sAcs[h][63]);
        __syncthreads();
    }
}

// ================= K4: inter-chunk scan (in-place prev) ======================
__global__ void k_scan()
{
    int h = blockIdx.x, b = blockIdx.y, dir = blockIdx.z;
    int tid = threadIdx.x;
    float carry[16];
    #pragma unroll
    for (int k = 0; k < 16; k++) carry[k] = 0.f;
    for (int c = 0; c < NC; c++) {
        float cdv = g_cd[dir][(b*NH + h)*NC + c];
        int sbase = ((b*NC + c)*NH + h) * 4096;
        #pragma unroll
        for (int k = 0; k < 16; k++) {
            int e = tid + k*256;
            float tmp = g_st[dir][sbase + e];
            g_st[dir][sbase + e] = carry[k];
            carry[k] = carry[k] * cdv + tmp;
        }
    }
}

// ================= K5: off-diag + gate + RMSnorm + out_proj (both dirs) ======
// dyn smem floats: sPrevT[64][260] | sY[64][260] | sC[64][68] | sWo[128][68] |
//                  sdt 256 | sAcs 256 | sE 256 | sScale 64   => 47168 floats
#define OUT_SMEM (47168*4)
__global__ __launch_bounds__(256) void k_out(
    const float* __restrict__ Al_f, const float* __restrict__ Al_b,
    const float* __restrict__ D_f,  const float* __restrict__ D_b,
    const float* __restrict__ nw_f, const float* __restrict__ nw_b,
    const float* __restrict__ Wo_f, const float* __restrict__ Wo_b,
    float* __restrict__ out)
{
    extern __shared__ float sm[];
    float (*sPrevT)[260] = (float(*)[260])sm;                       // [n][h*64+p]
    float (*sY)[260]     = (float(*)[260])(sm + 16640);
    float (*sC)[68]      = (float(*)[68])(sm + 33280);
    float (*sWo)[68]     = (float(*)[68])(sm + 37632);
    float (*sdt)[4]      = (float(*)[4])(sm + 46336);
    float (*sAcs)[64]    = (float(*)[64])(sm + 46592);
    float (*sE)[64]      = (float(*)[64])(sm + 46848);
    float *sScale        = sm + 47104;

    int c = blockIdx.x, b = blockIdx.y;
    int tid = threadIdx.x;
    float accO[4][8] = {};   // output tile l(4) x k(8), summed over both dirs

    for (int d = 0; d < 2; d++) {
        int cc = d ? (NC - 1 - c) : c;
        int base = b*SEQL + cc*CH;
        const float* Alog = d ? Al_b : Al_f;
        const float* Dp   = d ? D_b  : D_f;
        const float* nw   = d ? nw_b : nw_f;
        const float* Wo   = d ? Wo_b : Wo_f;
        const float* gx   = g_xbc[d];

        __syncthreads();
        { int l = tid >> 2, h = tid & 3; sdt[l][h] = g_dt[d][base*NH + tid]; }
        __syncthreads();
        if (tid < 4) {
            float A = -__expf(Alog[tid]);
            float run = 0.f;
            for (int l = 0; l < 64; l++) { run += sdt[l][tid] * A; sAcs[tid][l] = run; }
        }
        __syncthreads();
        { int h = tid >> 6, l = tid & 63; sE[h][l] = __expf(sAcs[h][l]); }
        // load C and prev (transposed to [n][h*64+p])
        #pragma unroll
        for (int it = 0; it < 4; it++) {
            int q = tid + it*256;
            int row = q >> 4, nq = (q & 15) * 4;
            *(float4*)&sC[row][nq] = *(const float4*)&gx[(base+row)*DX + DI + DS + nq];
        }
        {
            int pbase = (b*NC + cc)*NH*4096;
            #pragma unroll
            for (int it = 0; it < 16; it++) {
                int q = tid + it*256;
                int row = q >> 4, pq = (q & 15) * 4;   // row = h*64+n
                float4 v = *(const float4*)&g_st[d][pbase + row*64 + pq];
                *(float4*)&sPrevT[row & 63][(row >> 6)*64 + pq] = v;
            }
        }
        __syncthreads();

        // off-diag Yo + combine + gate  thread: 4l(tl) x [4 heads x 4p(hq)]
        {
            int tl = tid >> 4, hq = tid & 15;
            float4 acc[4][4] = {};   // [i=l][j=h]
            for (int n = 0; n < 64; n++) {
                float cv0 = sC[tl*4+0][n], cv1 = sC[tl*4+1][n];
                float cv2 = sC[tl*4+2][n], cv3 = sC[tl*4+3][n];
                #pragma unroll
                for (int j = 0; j < 4; j++) {
                    float4 p4 = *(float4*)&sPrevT[n][j*64 + hq*4];
                    fma4(acc[0][j], cv0, p4);
                    fma4(acc[1][j], cv1, p4);
                    fma4(acc[2][j], cv2, p4);
                    fma4(acc[3][j], cv3, p4);
                }
            }
            #pragma unroll
            for (int i = 0; i < 4; i++) {
                int l = tl*4 + i;
                int row = base + l;
                #pragma unroll
                for (int j = 0; j < 4; j++) {
                    int col = j*64 + hq*4;
                    float4 yd = *(const float4*)&g_yd[d][row*DI + col];
                    float4 xs = *(const float4*)&gx[row*DX + col];
                    float4 z4 = *(const float4*)&g_z[d][row*DI + col];
                    float e = sE[j][l], Dv = Dp[j];
                    float4 y;
                    y.x = (yd.x + e*acc[i][j].x + Dv*xs.x) * siluf(z4.x);
                    y.y = (yd.y + e*acc[i][j].y + Dv*xs.y) * siluf(z4.y);
                    y.z = (yd.z + e*acc[i][j].z + Dv*xs.z) * siluf(z4.z);
                    y.w = (yd.w + e*acc[i][j].w + Dv*xs.w) * siluf(z4.w);
                    *(float4*)&sY[l][col] = y;
                }
            }
        }
        __syncthreads();

        // RMSnorm: 4 threads per row
        {
            int lr = tid >> 2, part = tid & 3;
            float s = 0.f;
            #pragma unroll
            for (int q = 0; q < 16; q++) {
                float4 v = *(float4*)&sY[lr][part*64 + q*4];
                s += dot4(v, v);
            }
            s += __shfl_xor_sync(0xffffffff, s, 1);
            s += __shfl_xor_sync(0xffffffff, s, 2);
            float scale = rsqrtf(s * (1.f/256.f) + 1e-5f);
            if (part == 0) sScale[lr] = scale;
            #pragma unroll
            for (int q = 0; q < 16; q++) {
                int col = part*64 + q*4;
                float4 v = *(float4*)&sY[lr][col];
                float4 w = *(const float4*)&nw[col];
                v.x *= scale*w.x; v.y *= scale*w.y; v.z *= scale*w.z; v.w *= scale*w.w;
                *(float4*)&sY[lr][col] = v;
            }
        }
        __syncthreads();

        // out_proj: accumulate into accO with l-flip for dir 1
        {
            int tl2 = tid & 15, tk = tid >> 4;
            for (int jc = 0; jc < 4; jc++) {
                #pragma unroll
                for (int it = 0; it < 8; it++) {
                    int q = tid + it*256;
                    int row = q >> 4, jq = (q & 15) * 4;
                    *(float4*)&sWo[row][jq] = *(const float4*)&Wo[row*256 + jc*64 + jq];
                }
                __syncthreads();
                #pragma unroll
                for (int j4 = 0; j4 < 16; j4++) {
                    float4 y4[4];
                    #pragma unroll
                    for (int i = 0; i < 4; i++) {
                        int l = tl2*4 + i;
                        int lsrc = d ? (63 - l) : l;
                        y4[i] = *(float4*)&sY[lsrc][jc*64 + j4*4];
                    }
                    #pragma unroll
                    for (int kk = 0; kk < 8; kk++) {
                        float4 w4 = *(float4*)&sWo[tk*8 + kk][j4*4];
                        #pragma unroll
                        for (int i = 0; i < 4; i++) accO[i][kk] += dot4(y4[i], w4);
                    }
                }
                __syncthreads();
            }
        }
    }
    // store: rows t = c*CH + l  (dir-combined)
    {
        int tl2 = tid & 15, tk = tid >> 4;
        #pragma unroll
        for (int i = 0; i < 4; i++) {
            int t = c*CH + tl2*4 + i;
            float4 v0 = make_float4(accO[i][0], accO[i][1], accO[i][2], accO[i][3]);
            float4 v1 = make_float4(accO[i][4], accO[i][5], accO[i][6], accO[i][7]);
            *(float4*)&out[(b*SEQL + t)*DM + tk*8 + 0] = v0;
            *(float4*)&out[(b*SEQL + t)*DM + tk*8 + 4] = v1;
        }
    }
}

extern "C" void kernel_launch(void* const* d_in, const int* in_sizes, int n_in,
                              void* d_out, int out_size)
{
    const float* x    = (const float*)d_in[0];
    const float* Wi_f = (const float*)d_in[1];
    const float* cw_f = (const float*)d_in[2];
    const float* cb_f = (const float*)d_in[3];
    const float* db_f = (const float*)d_in[4];
    const float* Al_f = (const float*)d_in[5];
    const float* D_f  = (const float*)d_in[6];
    const float* nw_f = (const float*)d_in[7];
    const float* Wo_f = (const float*)d_in[8];
    const float* Wi_b = (const float*)d_in[9];
    const float* cw_b = (const float*)d_in[10];
    const float* cb_b = (const float*)d_in[11];
    const float* db_b = (const float*)d_in[12];
    const float* Al_b = (const float*)d_in[13];
    const float* D_b  = (const float*)d_in[14];
    const float* nw_b = (const float*)d_in[15];
    const float* Wo_b = (const float*)d_in[16];
    float* out = (float*)d_out;

    cudaFuncSetAttribute(k_inproj, cudaFuncAttributeMaxDynamicSharedMemorySize, IP_SMEM);
    cudaFuncSetAttribute(k_chunk,  cudaFuncAttributeMaxDynamicSharedMemorySize, CH_SMEM);
    cudaFuncSetAttribute(k_out,    cudaFuncAttributeMaxDynamicSharedMemorySize, OUT_SMEM);

    dim3 g1(BL/128, (NPROJ + 63)/64, 2);
    k_inproj<<<g1, 256, IP_SMEM>>>(x, Wi_f, Wi_b, db_f, db_b);

    dim3 g2((BL*DX/4 + 255)/256, 2);
    k_conv<<<g2, 256>>>(cw_f, cb_f, cw_b, cb_b);

    dim3 g3(NC, BATCH, 2);
    k_chunk<<<g3, 256, CH_SMEM>>>(Al_f, Al_b);

    dim3 g4(NH, BATCH, 2);
    k_scan<<<g4, 256>>>();

    dim3 g5(NC, BATCH);
    k_out<<<g5, 256, OUT_SMEM>>>(Al_f, Al_b, D_f, D_b, nw_f, nw_b, Wo_f, Wo_b, out);
}

// round 3
// speedup vs baseline: 9.2680x; 1.5127x over previous
#include <cuda_runtime.h>
#include <math.h>

#define BATCH 16
#define SEQL  2048
#define BL    (BATCH*SEQL)      // 32768
#define DM    128
#define DI    256
#define DX    384
#define NH    4
#define HD    64
#define DS    64
#define CH    64
#define NC    32
#define NPROJ 644

// ---------------- scratch ----------------------------------------------------
__device__ float g_z[2][BL*DI];
__device__ float g_xbc0[2][BL*DX];
__device__ float g_xbc[2][BL*DX];
__device__ float g_dt[2][BL*NH];
__device__ float g_st[2][BATCH*NC*NH*HD*DS];   // per h: [n][p] (transposed)
__device__ float g_yd[2][BL*DI];
__device__ float g_cd[2][BATCH*NH*NC];

__device__ __forceinline__ float softplusf(float x){ return x > 20.f ? x : log1pf(__expf(x)); }
__device__ __forceinline__ float siluf(float x){ return x / (1.f + __expf(-x)); }
__device__ __forceinline__ float dot4(float4 a, float4 b){
    return a.x*b.x + a.y*b.y + a.z*b.z + a.w*b.w;
}
__device__ __forceinline__ void fma4(float4& acc, float s, float4 v){
    acc.x += s*v.x; acc.y += s*v.y; acc.z += s*v.z; acc.w += s*v.w;
}

// ================= K1: in_proj GEMM (x @ Wi^T), time-flip for dir=1 ==========
// tile 128m x 64n, K=128 in two 64-chunks. 256 threads, per-thread 8m x 4n.
#define IP_SMEM ((128*68 + 64*68)*4)
__global__ __launch_bounds__(256) void k_inproj(
    const float* __restrict__ x,
    const float* __restrict__ Wi_f, const float* __restrict__ Wi_b,
    const float* __restrict__ db_f, const float* __restrict__ db_b)
{
    extern __shared__ float sm[];
    float (*sX)[68] = (float(*)[68])sm;            // [128][68]
    float (*sW)[68] = (float(*)[68])(sm + 128*68); // [64][68]
    int dir = blockIdx.z;
    const float* Wi = dir ? Wi_b : Wi_f;
    const float* db = dir ? db_b : db_f;
    int tid = threadIdx.x;
    int m0 = blockIdx.x * 128;
    int n0 = blockIdx.y * 64;
    int tm = tid & 15, tn = tid >> 4;
    float acc[8][4] = {};

    for (int kk = 0; kk < 2; kk++) {
        #pragma unroll
        for (int it = 0; it < 8; it++) {
            int q = tid + it*256;
            int row = q >> 4, kq = (q & 15) * 4;
            int m = m0 + row;
            int xr = dir ? ((m & ~2047) + 2047 - (m & 2047)) : m;
            *(float4*)&sX[row][kq] = *(const float4*)&x[xr*128 + kk*64 + kq];
        }
        #pragma unroll
        for (int it = 0; it < 4; it++) {
            int q = tid + it*256;
            int row = q >> 4, kq = (q & 15) * 4;
            int n = n0 + row;
            float4 v = make_float4(0.f,0.f,0.f,0.f);
            if (n < NPROJ) v = *(const float4*)&Wi[n*128 + kk*64 + kq];
            *(float4*)&sW[row][kq] = v;
        }
        __syncthreads();
        #pragma unroll
        for (int k4 = 0; k4 < 16; k4++) {
            float4 b4[4];
            #pragma unroll
            for (int j = 0; j < 4; j++) b4[j] = *(float4*)&sW[tn*4 + j][k4*4];
            #pragma unroll
            for (int i = 0; i < 8; i++) {
                float4 a = *(float4*)&sX[tm + 16*i][k4*4];
                #pragma unroll
                for (int j = 0; j < 4; j++) acc[i][j] += dot4(a, b4[j]);
            }
        }
        __syncthreads();
    }
    int nb = n0 + tn*4;
    #pragma unroll
    for (int i = 0; i < 8; i++) {
        int m = m0 + tm + 16*i;
        float4 v = make_float4(acc[i][0], acc[i][1], acc[i][2], acc[i][3]);
        if (nb < DI) {
            *(float4*)&g_z[dir][m*DI + nb] = v;
        } else if (nb < DI + DX) {
            *(float4*)&g_xbc0[dir][m*DX + (nb - DI)] = v;
        } else if (nb == DI + DX) {
            g_dt[dir][m*NH + 0] = softplusf(v.x + db[0]);
            g_dt[dir][m*NH + 1] = softplusf(v.y + db[1]);
            g_dt[dir][m*NH + 2] = softplusf(v.z + db[2]);
            g_dt[dir][m*NH + 3] = softplusf(v.w + db[3]);
        }
    }
}

// ================= K2: causal depthwise conv(4) + bias + silu (float4) =======
__global__ void k_conv(const float* __restrict__ cw_f, const float* __restrict__ cb_f,
                       const float* __restrict__ cw_b, const float* __restrict__ cb_b)
{
    int dir = blockIdx.y;
    const float* cw = dir ? cw_b : cw_f;
    const float* cb = dir ? cb_b : cb_f;
    int idx = blockIdx.x * 256 + threadIdx.x;   // quad index
    if (idx >= BL * DX / 4) return;
    int m = idx / (DX/4);
    int j = (idx - m * (DX/4)) * 4;
    int t = m & 2047;
    float4 acc = *(const float4*)&cb[j];
    float w[4][4];
    #pragma unroll
    for (int c = 0; c < 4; c++) {
        float4 wv = *(const float4*)&cw[(j + c) * 4];
        w[c][0] = wv.x; w[c][1] = wv.y; w[c][2] = wv.z; w[c][3] = wv.w;
    }
    #pragma unroll
    for (int k = 0; k < 4; k++) {
        int tt = t - 3 + k;
        if (tt >= 0) {
            float4 v = *(const float4*)&g_xbc0[dir][(m - 3 + k)*DX + j];
            acc.x += v.x * w[0][k];
            acc.y += v.y * w[1][k];
            acc.z += v.z * w[2][k];
            acc.w += v.w * w[3][k];
        }
    }
    acc.x = siluf(acc.x); acc.y = siluf(acc.y); acc.z = siluf(acc.z); acc.w = siluf(acc.w);
    *(float4*)&g_xbc[dir][m*DX + j] = acc;
}

// ================= K3: per-chunk diagonal block + chunk state ================
// dyn smem floats: sB[64][68] | sW[64][68] (first holds C) | sX[64][260] |
//                  sdt 256 | sAcs 256 | sdec 64   => 25920 floats
#define CH_SMEM (25920*4)
__global__ __launch_bounds__(256) void k_chunk(const float* __restrict__ Al_f,
                                               const float* __restrict__ Al_b)
{
    extern __shared__ float sm[];
    float (*sB)[68]   = (float(*)[68])sm;
    float (*sW)[68]   = (float(*)[68])(sm + 64*68);           // C, then W per head
    float (*sX)[260]  = (float(*)[260])(sm + 2*64*68);
    float (*sdt)[4]   = (float(*)[4])(sm + 2*64*68 + 64*260);
    float (*sAcs)[64] = (float(*)[64])(sm + 2*64*68 + 64*260 + 256);
    float *sdec       = sm + 2*64*68 + 64*260 + 512;

    int c = blockIdx.x, b = blockIdx.y, dir = blockIdx.z;
    const float* gx = g_xbc[dir];
    int tid = threadIdx.x;
    int base = b*SEQL + c*CH;

    { int l = tid >> 2, h = tid & 3; sdt[l][h] = g_dt[dir][base*NH + tid]; }
    #pragma unroll
    for (int it = 0; it < 4; it++) {
        int q = tid + it*256;
        int row = q >> 4, nq = (q & 15) * 4;
        *(float4*)&sB[row][nq] = *(const float4*)&gx[(base+row)*DX + DI + nq];
        *(float4*)&sW[row][nq] = *(const float4*)&gx[(base+row)*DX + DI + DS + nq]; // C
    }
    __syncthreads();
    #pragma unroll
    for (int it = 0; it < 16; it++) {
        int q = tid + it*256;
        int row = q >> 6, qq = (q & 63) * 4;
        float4 v = *(const float4*)&gx[(base+row)*DX + qq];
        float dtv = sdt[row][qq >> 6];
        v.x *= dtv; v.y *= dtv; v.z *= dtv; v.w *= dtv;
        *(float4*)&sX[row][qq] = v;
    }
    if (tid < 4) {
        float A = -__expf((dir ? Al_b : Al_f)[tid]);
        float run = 0.f;
        for (int l = 0; l < 64; l++) { run += sdt[l][tid] * A; sAcs[tid][l] = run; }
    }
    __syncthreads();

    // CB tile (4l x 4s) into registers; sW currently holds C
    int ts = tid & 15, tl = tid >> 4;
    float cb[4][4] = {};
    if (ts <= tl) {
        #pragma unroll
        for (int nq = 0; nq < 16; nq++) {
            float4 a4[4], b4[4];
            #pragma unroll
            for (int i = 0; i < 4; i++) a4[i] = *(float4*)&sW[tl*4 + i][nq*4];
            #pragma unroll
            for (int j = 0; j < 4; j++) b4[j] = *(float4*)&sB[ts*4 + j][nq*4];
            #pragma unroll
            for (int i = 0; i < 4; i++)
                #pragma unroll
                for (int j = 0; j < 4; j++) cb[i][j] += dot4(a4[i], b4[j]);
        }
    }
    __syncthreads();   // all C reads done; sW becomes the L-masked matrix

    int sbase = (b*NC + c)*NH*4096;
    for (int h = 0; h < NH; h++) {
        #pragma unroll
        for (int i = 0; i < 4; i++) {
            int l = tl*4 + i;
            float al = sAcs[h][l];
            float4 w;
            w.x = (ts*4+0 <= l) ? cb[i][0] * __expf(al - sAcs[h][ts*4+0]) : 0.f;
            w.y = (ts*4+1 <= l) ? cb[i][1] * __expf(al - sAcs[h][ts*4+1]) : 0.f;
            w.z = (ts*4+2 <= l) ? cb[i][2] * __expf(al - sAcs[h][ts*4+2]) : 0.f;
            w.w = (ts*4+3 <= l) ? cb[i][3] * __expf(al - sAcs[h][ts*4+3]) : 0.f;
            *(float4*)&sW[l][ts*4] = w;
        }
        if (tid < 64) sdec[tid] = __expf(sAcs[h][63] - sAcs[h][tid]);
        __syncthreads();

        // Y_diag: (CB .* L) @ Xdt   thread: 4l x 4p
        {
            float4 acc[4] = {};
            for (int sq = 0; sq <= tl; sq++) {
                float4 x0 = *(float4*)&sX[sq*4+0][h*64 + ts*4];
                float4 x1 = *(float4*)&sX[sq*4+1][h*64 + ts*4];
                float4 x2 = *(float4*)&sX[sq*4+2][h*64 + ts*4];
                float4 x3 = *(float4*)&sX[sq*4+3][h*64 + ts*4];
                #pragma unroll
                for (int i = 0; i < 4; i++) {
                    float4 w4 = *(float4*)&sW[tl*4 + i][sq*4];
                    fma4(acc[i], w4.x, x0);
                    fma4(acc[i], w4.y, x1);
                    fma4(acc[i], w4.z, x2);
                    fma4(acc[i], w4.w, x3);
                }
            }
            #pragma unroll
            for (int i = 0; i < 4; i++)
                *(float4*)&g_yd[dir][(base + tl*4 + i)*DI + h*64 + ts*4] = acc[i];
        }
        // chunk state st[n][p] (transposed store)  thread: 4p(tl) x 4n(ts)
        {
            float st[4][4] = {};   // [p][n]
            for (int l = 0; l < 64; l++) {
                float d = sdec[l];
                float4 x4 = *(float4*)&sX[l][h*64 + tl*4];
                float4 b4 = *(float4*)&sB[l][ts*4];
                x4.x *= d; x4.y *= d; x4.z *= d; x4.w *= d;
                st[0][0] += x4.x*b4.x; st[0][1] += x4.x*b4.y; st[0][2] += x4.x*b4.z; st[0][3] += x4.x*b4.w;
                st[1][0] += x4.y*b4.x; st[1][1] += x4.y*b4.y; st[1][2] += x4.y*b4.z; st[1][3] += x4.y*b4.w;
                st[2][0] += x4.z*b4.x; st[2][1] += x4.z*b4.y; st[2][2] += x4.z*b4.z; st[2][3] += x4.z*b4.w;
                st[3][0] += x4.w*b4.x; st[3][1] += x4.w*b4.y; st[3][2] += x4.w*b4.z; st[3][3] += x4.w*b4.w;
            }
            #pragma unroll
            for (int j = 0; j < 4; j++) {
                float4 v = make_float4(st[0][j], st[1][j], st[2][j], st[3][j]);
                *(float4*)&g_st[dir][sbase + h*4096 + (ts*4 + j)*64 + tl*4] = v;
            }
        }
        if (tid == 0) g_cd[dir][(b*NH + h)*NC + c] = __expf(sAcs[h][63]);
        __syncthreads();
    }
}

// ================= K4: inter-chunk scan — pipelined, vectorized ==============
// grid: (4 element-groups, BATCH*NH, 2), 256 threads, float4 per thread.
__global__ __launch_bounds__(256) void k_scan()
{
    int grp = blockIdx.x;               // 0..3 : which 1024-element slice
    int bh  = blockIdx.y;               // b*NH + h
    int dir = blockIdx.z;
    int h = bh & 3, b = bh >> 2;
    int tid = threadIdx.x;
    int e0 = grp*1024 + tid*4;          // element offset within the 4096 state

    float cd[NC];
    #pragma unroll
    for (int c = 0; c < NC; c++) cd[c] = g_cd[dir][(b*NH + h)*NC + c];

    // addresses: ((b*NC + c)*NH + h)*4096 + e0 ; stride between chunks = NH*4096
    float* p = &g_st[dir][(b*NC*NH + h)*4096 + e0];
    const int cstride = NH*4096;

    float4 carry = make_float4(0.f, 0.f, 0.f, 0.f);
    float4 nxt = *(float4*)p;
    #pragma unroll
    for (int c = 0; c < NC; c++) {
        float4 cur = nxt;
        if (c + 1 < NC) nxt = *(float4*)(p + (c+1)*cstride);   // prefetch next chunk
        *(float4*)(p + c*cstride) = carry;                     // prev state for chunk c
        float d = cd[c];
        carry.x = carry.x*d + cur.x;
        carry.y = carry.y*d + cur.y;
        carry.z = carry.z*d + cur.z;
        carry.w = carry.w*d + cur.w;
    }
}

// ================= K5: off-diag + gate + RMSnorm + out_proj (both dirs) ======
// dyn smem floats: sPrevT[64][260] | sY[64][260] | sC[64][68] | sWo[128][68] |
//                  sdt 256 | sAcs 256 | sE 256 | sScale 64   => 47168 floats
#define OUT_SMEM (47168*4)
__global__ __launch_bounds__(256) void k_out(
    const float* __restrict__ Al_f, const float* __restrict__ Al_b,
    const float* __restrict__ D_f,  const float* __restrict__ D_b,
    const float* __restrict__ nw_f, const float* __restrict__ nw_b,
    const float* __restrict__ Wo_f, const float* __restrict__ Wo_b,
    float* __restrict__ out)
{
    extern __shared__ float sm[];
    float (*sPrevT)[260] = (float(*)[260])sm;                       // [n][h*64+p]
    float (*sY)[260]     = (float(*)[260])(sm + 16640);
    float (*sC)[68]      = (float(*)[68])(sm + 33280);
    float (*sWo)[68]     = (float(*)[68])(sm + 37632);
    float (*sdt)[4]      = (float(*)[4])(sm + 46336);
    float (*sAcs)[64]    = (float(*)[64])(sm + 46592);
    float (*sE)[64]      = (float(*)[64])(sm + 46848);
    float *sScale        = sm + 47104;

    int c = blockIdx.x, b = blockIdx.y;
    int tid = threadIdx.x;
    float accO[4][8] = {};   // output tile l(4) x k(8), summed over both dirs

    for (int d = 0; d < 2; d++) {
        int cc = d ? (NC - 1 - c) : c;
        int base = b*SEQL + cc*CH;
        const float* Alog = d ? Al_b : Al_f;
        const float* Dp   = d ? D_b  : D_f;
        const float* nw   = d ? nw_b : nw_f;
        const float* Wo   = d ? Wo_b : Wo_f;
        const float* gx   = g_xbc[d];

        __syncthreads();
        { int l = tid >> 2, h = tid & 3; sdt[l][h] = g_dt[d][base*NH + tid]; }
        __syncthreads();
        if (tid < 4) {
            float A = -__expf(Alog[tid]);
            float run = 0.f;
            for (int l = 0; l < 64; l++) { run += sdt[l][tid] * A; sAcs[tid][l] = run; }
        }
        __syncthreads();
        { int h = tid >> 6, l = tid & 63; sE[h][l] = __expf(sAcs[h][l]); }
        // load C and prev (transposed to [n][h*64+p])
        #pragma unroll
        for (int it = 0; it < 4; it++) {
            int q = tid + it*256;
            int row = q >> 4, nq = (q & 15) * 4;
            *(float4*)&sC[row][nq] = *(const float4*)&gx[(base+row)*DX + DI + DS + nq];
        }
        {
            int pbase = (b*NC + cc)*NH*4096;
            #pragma unroll
            for (int it = 0; it < 16; it++) {
                int q = tid + it*256;
                int row = q >> 4, pq = (q & 15) * 4;   // row = h*64+n
                float4 v = *(const float4*)&g_st[d][pbase + row*64 + pq];
                *(float4*)&sPrevT[row & 63][(row >> 6)*64 + pq] = v;
            }
        }
        __syncthreads();

        // off-diag Yo + combine + gate  thread: 4l(tl) x [4 heads x 4p(hq)]
        {
            int tl = tid >> 4, hq = tid & 15;
            float4 acc[4][4] = {};   // [i=l][j=h]
            for (int n = 0; n < 64; n++) {
                float cv0 = sC[tl*4+0][n], cv1 = sC[tl*4+1][n];
                float cv2 = sC[tl*4+2][n], cv3 = sC[tl*4+3][n];
                #pragma unroll
                for (int j = 0; j < 4; j++) {
                    float4 p4 = *(float4*)&sPrevT[n][j*64 + hq*4];
                    fma4(acc[0][j], cv0, p4);
                    fma4(acc[1][j], cv1, p4);
                    fma4(acc[2][j], cv2, p4);
                    fma4(acc[3][j], cv3, p4);
                }
            }
            #pragma unroll
            for (int i = 0; i < 4; i++) {
                int l = tl*4 + i;
                int row = base + l;
                #pragma unroll
                for (int j = 0; j < 4; j++) {
                    int col = j*64 + hq*4;
                    float4 yd = *(const float4*)&g_yd[d][row*DI + col];
                    float4 xs = *(const float4*)&gx[row*DX + col];
                    float4 z4 = *(const float4*)&g_z[d][row*DI + col];
                    float e = sE[j][l], Dv = Dp[j];
                    float4 y;
                    y.x = (yd.x + e*acc[i][j].x + Dv*xs.x) * siluf(z4.x);
                    y.y = (yd.y + e*acc[i][j].y + Dv*xs.y) * siluf(z4.y);
                    y.z = (yd.z + e*acc[i][j].z + Dv*xs.z) * siluf(z4.z);
                    y.w = (yd.w + e*acc[i][j].w + Dv*xs.w) * siluf(z4.w);
                    *(float4*)&sY[l][col] = y;
                }
            }
        }
        __syncthreads();

        // RMSnorm: 4 threads per row
        {
            int lr = tid >> 2, part = tid & 3;
            float s = 0.f;
            #pragma unroll
            for (int q = 0; q < 16; q++) {
                float4 v = *(float4*)&sY[lr][part*64 + q*4];
                s += dot4(v, v);
            }
            s += __shfl_xor_sync(0xffffffff, s, 1);
            s += __shfl_xor_sync(0xffffffff, s, 2);
            float scale = rsqrtf(s * (1.f/256.f) + 1e-5f);
            if (part == 0) sScale[lr] = scale;
            #pragma unroll
            for (int q = 0; q < 16; q++) {
                int col = part*64 + q*4;
                float4 v = *(float4*)&sY[lr][col];
                float4 w = *(const float4*)&nw[col];
                v.x *= scale*w.x; v.y *= scale*w.y; v.z *= scale*w.z; v.w *= scale*w.w;
                *(float4*)&sY[lr][col] = v;
            }
        }
        __syncthreads();

        // out_proj: accumulate into accO with l-flip for dir 1
        {
            int tl2 = tid & 15, tk = tid >> 4;
            for (int jc = 0; jc < 4; jc++) {
                #pragma unroll
                for (int it = 0; it < 8; it++) {
                    int q = tid + it*256;
                    int row = q >> 4, jq = (q & 15) * 4;
                    *(float4*)&sWo[row][jq] = *(const float4*)&Wo[row*256 + jc*64 + jq];
                }
                __syncthreads();
                #pragma unroll
                for (int j4 = 0; j4 < 16; j4++) {
                    float4 y4[4];
                    #pragma unroll
                    for (int i = 0; i < 4; i++) {
                        int l = tl2*4 + i;
                        int lsrc = d ? (63 - l) : l;
                        y4[i] = *(float4*)&sY[lsrc][jc*64 + j4*4];
                    }
                    #pragma unroll
                    for (int kk = 0; kk < 8; kk++) {
                        float4 w4 = *(float4*)&sWo[tk*8 + kk][j4*4];
                        #pragma unroll
                        for (int i = 0; i < 4; i++) accO[i][kk] += dot4(y4[i], w4);
                    }
                }
                __syncthreads();
            }
        }
    }
    // store: rows t = c*CH + l  (dir-combined)
    {
        int tl2 = tid & 15, tk = tid >> 4;
        #pragma unroll
        for (int i = 0; i < 4; i++) {
            int t = c*CH + tl2*4 + i;
            float4 v0 = make_float4(accO[i][0], accO[i][1], accO[i][2], accO[i][3]);
            float4 v1 = make_float4(accO[i][4], accO[i][5], accO[i][6], accO[i][7]);
            *(float4*)&out[(b*SEQL + t)*DM + tk*8 + 0] = v0;
            *(float4*)&out[(b*SEQL + t)*DM + tk*8 + 4] = v1;
        }
    }
}

extern "C" void kernel_launch(void* const* d_in, const int* in_sizes, int n_in,
                              void* d_out, int out_size)
{
    const float* x    = (const float*)d_in[0];
    const float* Wi_f = (const float*)d_in[1];
    const float* cw_f = (const float*)d_in[2];
    const float* cb_f = (const float*)d_in[3];
    const float* db_f = (const float*)d_in[4];
    const float* Al_f = (const float*)d_in[5];
    const float* D_f  = (const float*)d_in[6];
    const float* nw_f = (const float*)d_in[7];
    const float* Wo_f = (const float*)d_in[8];
    const float* Wi_b = (const float*)d_in[9];
    const float* cw_b = (const float*)d_in[10];
    const float* cb_b = (const float*)d_in[11];
    const float* db_b = (const float*)d_in[12];
    const float* Al_b = (const float*)d_in[13];
    const float* D_b  = (const float*)d_in[14];
    const float* nw_b = (const float*)d_in[15];
    const float* Wo_b = (const float*)d_in[16];
    float* out = (float*)d_out;

    cudaFuncSetAttribute(k_inproj, cudaFuncAttributeMaxDynamicSharedMemorySize, IP_SMEM);
    cudaFuncSetAttribute(k_chunk,  cudaFuncAttributeMaxDynamicSharedMemorySize, CH_SMEM);
    cudaFuncSetAttribute(k_out,    cudaFuncAttributeMaxDynamicSharedMemorySize, OUT_SMEM);

    dim3 g1(BL/128, (NPROJ + 63)/64, 2);
    k_inproj<<<g1, 256, IP_SMEM>>>(x, Wi_f, Wi_b, db_f, db_b);

    dim3 g2((BL*DX/4 + 255)/256, 2);
    k_conv<<<g2, 256>>>(cw_f, cb_f, cw_b, cb_b);

    dim3 g3(NC, BATCH, 2);
    k_chunk<<<g3, 256, CH_SMEM>>>(Al_f, Al_b);

    dim3 g4(4, BATCH*NH, 2);
    k_scan<<<g4, 256>>>();

    dim3 g5(NC, BATCH);
    k_out<<<g5, 256, OUT_SMEM>>>(Al_f, Al_b, D_f, D_b, nw_f, nw_b, Wo_f, Wo_b, out);
}

// round 4
// speedup vs baseline: 11.6778x; 1.2600x over previous
#include <cuda_runtime.h>
#include <math.h>

#define BATCH 16
#define SEQL  2048
#define BL    (BATCH*SEQL)      // 32768
#define DM    128
#define DI    256
#define DX    384
#define NH    4
#define HD    64
#define DS    64
#define CH    64
#define NC    32
#define NPROJ 644

// ---------------- scratch ----------------------------------------------------
__device__ float g_z[2][BL*DI];
__device__ float g_xbc0[2][BL*DX];
__device__ float g_xbc[2][BL*DX];
__device__ float g_dt[2][BL*NH];
__device__ float g_st[2][BATCH*NC*NH*HD*DS];   // per h: [n][p] (transposed)
__device__ float g_yd[2][BL*DI];
__device__ float g_cd[2][BATCH*NH*NC];

__device__ __forceinline__ float softplusf(float x){ return x > 20.f ? x : log1pf(__expf(x)); }
__device__ __forceinline__ float siluf(float x){ return x / (1.f + __expf(-x)); }
__device__ __forceinline__ float dot4(float4 a, float4 b){
    return a.x*b.x + a.y*b.y + a.z*b.z + a.w*b.w;
}
__device__ __forceinline__ void fma4(float4& acc, float s, float4 v){
    acc.x += s*v.x; acc.y += s*v.y; acc.z += s*v.z; acc.w += s*v.w;
}
__device__ __forceinline__ float f2tf32(float x){
    unsigned r;
    asm("cvt.rna.tf32.f32 %0, %1;" : "=r"(r) : "f"(x));
    return __uint_as_float(r);
}
__device__ __forceinline__ void mma_tf32(float c[4],
    unsigned a0, unsigned a1, unsigned a2, unsigned a3,
    unsigned b0, unsigned b1)
{
    asm("mma.sync.aligned.m16n8k8.row.col.f32.tf32.tf32.f32 "
        "{%0,%1,%2,%3}, {%4,%5,%6,%7}, {%8,%9}, {%0,%1,%2,%3};"
        : "+f"(c[0]), "+f"(c[1]), "+f"(c[2]), "+f"(c[3])
        : "r"(a0), "r"(a1), "r"(a2), "r"(a3), "r"(b0), "r"(b1));
}

// ================= K1: in_proj GEMM via tf32 MMA =============================
// block tile 128m x 64n, K=128 in two 64-chunks. 8 warps: 2(m) x 4(n),
// warp tile 64m x 16n -> 4 m-tiles x 2 n-tiles of m16n8k8.
#define IP_SMEM ((128*68 + 64*68)*4)

__device__ __forceinline__ void ip_store2(int dir, const float* db, int m, int c,
                                          float v0, float v1)
{
    if (c < DI) {
        float2 v = make_float2(v0, v1);
        *(float2*)&g_z[dir][m*DI + c] = v;
    } else if (c < DI + DX) {
        float2 v = make_float2(v0, v1);
        *(float2*)&g_xbc0[dir][m*DX + (c - DI)] = v;
    } else if (c < DI + DX + NH) {
        int h = c - DI - DX;
        g_dt[dir][m*NH + h]     = softplusf(v0 + db[h]);
        g_dt[dir][m*NH + h + 1] = softplusf(v1 + db[h + 1]);
    }
}

__global__ __launch_bounds__(256) void k_inproj(
    const float* __restrict__ x,
    const float* __restrict__ Wi_f, const float* __restrict__ Wi_b,
    const float* __restrict__ db_f, const float* __restrict__ db_b)
{
    extern __shared__ float sm[];
    float (*sX)[68] = (float(*)[68])sm;            // [128][68] tf32
    float (*sW)[68] = (float(*)[68])(sm + 128*68); // [64][68]  tf32
    int dir = blockIdx.z;
    const float* Wi = dir ? Wi_b : Wi_f;
    const float* db = dir ? db_b : db_f;
    int tid = threadIdx.x;
    int m0 = blockIdx.x * 128;
    int n0 = blockIdx.y * 64;
    int wid = tid >> 5, lane = tid & 31;
    int wm = wid & 1, wn = wid >> 1;        // warp coords: 2 x 4
    int gid = lane >> 2, tig = lane & 3;
    float acc[4][2][4] = {};

    for (int kk = 0; kk < 2; kk++) {
        #pragma unroll
        for (int it = 0; it < 8; it++) {
            int q = tid + it*256;
            int row = q >> 4, kq = (q & 15) * 4;
            int m = m0 + row;
            int xr = dir ? ((m & ~2047) + 2047 - (m & 2047)) : m;
            float4 v = *(const float4*)&x[xr*128 + kk*64 + kq];
            sX[row][kq+0] = f2tf32(v.x); sX[row][kq+1] = f2tf32(v.y);
            sX[row][kq+2] = f2tf32(v.z); sX[row][kq+3] = f2tf32(v.w);
        }
        #pragma unroll
        for (int it = 0; it < 4; it++) {
            int q = tid + it*256;
            int row = q >> 4, kq = (q & 15) * 4;
            int n = n0 + row;
            float4 v = make_float4(0.f,0.f,0.f,0.f);
            if (n < NPROJ) v = *(const float4*)&Wi[n*128 + kk*64 + kq];
            sW[row][kq+0] = f2tf32(v.x); sW[row][kq+1] = f2tf32(v.y);
            sW[row][kq+2] = f2tf32(v.z); sW[row][kq+3] = f2tf32(v.w);
        }
        __syncthreads();
        #pragma unroll
        for (int ks = 0; ks < 8; ks++) {
            int kb = ks*8;
            unsigned b[2][2];
            #pragma unroll
            for (int ni = 0; ni < 2; ni++) {
                int n = wn*16 + ni*8 + gid;
                b[ni][0] = __float_as_uint(sW[n][kb + tig]);
                b[ni][1] = __float_as_uint(sW[n][kb + tig + 4]);
            }
            #pragma unroll
            for (int mi = 0; mi < 4; mi++) {
                int r = wm*64 + mi*16 + gid;
                unsigned a0 = __float_as_uint(sX[r    ][kb + tig]);
                unsigned a1 = __float_as_uint(sX[r + 8][kb + tig]);
                unsigned a2 = __float_as_uint(sX[r    ][kb + tig + 4]);
                unsigned a3 = __float_as_uint(sX[r + 8][kb + tig + 4]);
                mma_tf32(acc[mi][0], a0, a1, a2, a3, b[0][0], b[0][1]);
                mma_tf32(acc[mi][1], a0, a1, a2, a3, b[1][0], b[1][1]);
            }
        }
        __syncthreads();
    }
    #pragma unroll
    for (int mi = 0; mi < 4; mi++) {
        int r0 = m0 + wm*64 + mi*16 + gid;
        #pragma unroll
        for (int ni = 0; ni < 2; ni++) {
            int c = n0 + wn*16 + ni*8 + tig*2;
            ip_store2(dir, db, r0,     c, acc[mi][ni][0], acc[mi][ni][1]);
            ip_store2(dir, db, r0 + 8, c, acc[mi][ni][2], acc[mi][ni][3]);
        }
    }
}

// ================= K2: causal depthwise conv(4) + bias + silu (float4) =======
__global__ void k_conv(const float* __restrict__ cw_f, const float* __restrict__ cb_f,
                       const float* __restrict__ cw_b, const float* __restrict__ cb_b)
{
    int dir = blockIdx.y;
    const float* cw = dir ? cw_b : cw_f;
    const float* cb = dir ? cb_b : cb_f;
    int idx = blockIdx.x * 256 + threadIdx.x;   // quad index
    if (idx >= BL * DX / 4) return;
    int m = idx / (DX/4);
    int j = (idx - m * (DX/4)) * 4;
    int t = m & 2047;
    float4 acc = *(const float4*)&cb[j];
    float w[4][4];
    #pragma unroll
    for (int c = 0; c < 4; c++) {
        float4 wv = *(const float4*)&cw[(j + c) * 4];
        w[c][0] = wv.x; w[c][1] = wv.y; w[c][2] = wv.z; w[c][3] = wv.w;
    }
    #pragma unroll
    for (int k = 0; k < 4; k++) {
        int tt = t - 3 + k;
        if (tt >= 0) {
            float4 v = *(const float4*)&g_xbc0[dir][(m - 3 + k)*DX + j];
            acc.x += v.x * w[0][k];
            acc.y += v.y * w[1][k];
            acc.z += v.z * w[2][k];
            acc.w += v.w * w[3][k];
        }
    }
    acc.x = siluf(acc.x); acc.y = siluf(acc.y); acc.z = siluf(acc.z); acc.w = siluf(acc.w);
    *(float4*)&g_xbc[dir][m*DX + j] = acc;
}

// ================= K3: per-chunk diagonal block + chunk state ================
// dyn smem floats: sB[64][68] | sW[64][68] (first holds C) | sX[64][260] |
//                  sdt 256 | sAcs 256 | sdec 64   => 25920 floats
#define CH_SMEM (25920*4)
__global__ __launch_bounds__(256) void k_chunk(const float* __restrict__ Al_f,
                                               const float* __restrict__ Al_b)
{
    extern __shared__ float sm[];
    float (*sB)[68]   = (float(*)[68])sm;
    float (*sW)[68]   = (float(*)[68])(sm + 64*68);           // C, then W per head
    float (*sX)[260]  = (float(*)[260])(sm + 2*64*68);
    float (*sdt)[4]   = (float(*)[4])(sm + 2*64*68 + 64*260);
    float (*sAcs)[64] = (float(*)[64])(sm + 2*64*68 + 64*260 + 256);
    float *sdec       = sm + 2*64*68 + 64*260 + 512;

    int c = blockIdx.x, b = blockIdx.y, dir = blockIdx.z;
    const float* gx = g_xbc[dir];
    int tid = threadIdx.x;
    int base = b*SEQL + c*CH;

    { int l = tid >> 2, h = tid & 3; sdt[l][h] = g_dt[dir][base*NH + tid]; }
    #pragma unroll
    for (int it = 0; it < 4; it++) {
        int q = tid + it*256;
        int row = q >> 4, nq = (q & 15) * 4;
        *(float4*)&sB[row][nq] = *(const float4*)&gx[(base+row)*DX + DI + nq];
        *(float4*)&sW[row][nq] = *(const float4*)&gx[(base+row)*DX + DI + DS + nq]; // C
    }
    __syncthreads();
    #pragma unroll
    for (int it = 0; it < 16; it++) {
        int q = tid + it*256;
        int row = q >> 6, qq = (q & 63) * 4;
        float4 v = *(const float4*)&gx[(base+row)*DX + qq];
        float dtv = sdt[row][qq >> 6];
        v.x *= dtv; v.y *= dtv; v.z *= dtv; v.w *= dtv;
        *(float4*)&sX[row][qq] = v;
    }
    if (tid < 4) {
        float A = -__expf((dir ? Al_b : Al_f)[tid]);
        float run = 0.f;
        for (int l = 0; l < 64; l++) { run += sdt[l][tid] * A; sAcs[tid][l] = run; }
    }
    __syncthreads();

    // CB tile (4l x 4s) into registers; sW currently holds C
    int ts = tid & 15, tl = tid >> 4;
    float cb[4][4] = {};
    if (ts <= tl) {
        #pragma unroll
        for (int nq = 0; nq < 16; nq++) {
            float4 a4[4], b4[4];
            #pragma unroll
            for (int i = 0; i < 4; i++) a4[i] = *(float4*)&sW[tl*4 + i][nq*4];
            #pragma unroll
            for (int j = 0; j < 4; j++) b4[j] = *(float4*)&sB[ts*4 + j][nq*4];
            #pragma unroll
            for (int i = 0; i < 4; i++)
                #pragma unroll
                for (int j = 0; j < 4; j++) cb[i][j] += dot4(a4[i], b4[j]);
        }
    }
    __syncthreads();   // all C reads done; sW becomes the L-masked matrix

    int sbase = (b*NC + c)*NH*4096;
    for (int h = 0; h < NH; h++) {
        #pragma unroll
        for (int i = 0; i < 4; i++) {
            int l = tl*4 + i;
            float al = sAcs[h][l];
            float4 w;
            w.x = (ts*4+0 <= l) ? cb[i][0] * __expf(al - sAcs[h][ts*4+0]) : 0.f;
            w.y = (ts*4+1 <= l) ? cb[i][1] * __expf(al - sAcs[h][ts*4+1]) : 0.f;
            w.z = (ts*4+2 <= l) ? cb[i][2] * __expf(al - sAcs[h][ts*4+2]) : 0.f;
            w.w = (ts*4+3 <= l) ? cb[i][3] * __expf(al - sAcs[h][ts*4+3]) : 0.f;
            *(float4*)&sW[l][ts*4] = w;
        }
        if (tid < 64) sdec[tid] = __expf(sAcs[h][63] - sAcs[h][tid]);
        __syncthreads();

        // Y_diag: (CB .* L) @ Xdt   thread: 4l x 4p
        {
            float4 acc[4] = {};
            for (int sq = 0; sq <= tl; sq++) {
                float4 x0 = *(float4*)&sX[sq*4+0][h*64 + ts*4];
                float4 x1 = *(float4*)&sX[sq*4+1][h*64 + ts*4];
                float4 x2 = *(float4*)&sX[sq*4+2][h*64 + ts*4];
                float4 x3 = *(float4*)&sX[sq*4+3][h*64 + ts*4];
                #pragma unroll
                for (int i = 0; i < 4; i++) {
                    float4 w4 = *(float4*)&sW[tl*4 + i][sq*4];
                    fma4(acc[i], w4.x, x0);
                    fma4(acc[i], w4.y, x1);
                    fma4(acc[i], w4.z, x2);
                    fma4(acc[i], w4.w, x3);
                }
            }
            #pragma unroll
            for (int i = 0; i < 4; i++)
                *(float4*)&g_yd[dir][(base + tl*4 + i)*DI + h*64 + ts*4] = acc[i];
        }
        // chunk state st[n][p] (transposed store)  thread: 4p(tl) x 4n(ts)
        {
            float st[4][4] = {};   // [p][n]
            for (int l = 0; l < 64; l++) {
                float d = sdec[l];
                float4 x4 = *(float4*)&sX[l][h*64 + tl*4];
                float4 b4 = *(float4*)&sB[l][ts*4];
                x4.x *= d; x4.y *= d; x4.z *= d; x4.w *= d;
                st[0][0] += x4.x*b4.x; st[0][1] += x4.x*b4.y; st[0][2] += x4.x*b4.z; st[0][3] += x4.x*b4.w;
                st[1][0] += x4.y*b4.x; st[1][1] += x4.y*b4.y; st[1][2] += x4.y*b4.z; st[1][3] += x4.y*b4.w;
                st[2][0] += x4.z*b4.x; st[2][1] += x4.z*b4.y; st[2][2] += x4.z*b4.z; st[2][3] += x4.z*b4.w;
                st[3][0] += x4.w*b4.x; st[3][1] += x4.w*b4.y; st[3][2] += x4.w*b4.z; st[3][3] += x4.w*b4.w;
            }
            #pragma unroll
            for (int j = 0; j < 4; j++) {
                float4 v = make_float4(st[0][j], st[1][j], st[2][j], st[3][j]);
                *(float4*)&g_st[dir][sbase + h*4096 + (ts*4 + j)*64 + tl*4] = v;
            }
        }
        if (tid == 0) g_cd[dir][(b*NH + h)*NC + c] = __expf(sAcs[h][63]);
        __syncthreads();
    }
}

// ================= K4: inter-chunk scan — pipelined, vectorized ==============
__global__ __launch_bounds__(256) void k_scan()
{
    int grp = blockIdx.x;               // 0..3 : which 1024-element slice
    int bh  = blockIdx.y;               // b*NH + h
    int dir = blockIdx.z;
    int h = bh & 3, b = bh >> 2;
    int tid = threadIdx.x;
    int e0 = grp*1024 + tid*4;

    float cd[NC];
    #pragma unroll
    for (int c = 0; c < NC; c++) cd[c] = g_cd[dir][(b*NH + h)*NC + c];

    float* p = &g_st[dir][(b*NC*NH + h)*4096 + e0];
    const int cstride = NH*4096;

    float4 carry = make_float4(0.f, 0.f, 0.f, 0.f);
    float4 nxt = *(float4*)p;
    #pragma unroll
    for (int c = 0; c < NC; c++) {
        float4 cur = nxt;
        if (c + 1 < NC) nxt = *(float4*)(p + (c+1)*cstride);
        *(float4*)(p + c*cstride) = carry;
        float d = cd[c];
        carry.x = carry.x*d + cur.x;
        carry.y = carry.y*d + cur.y;
        carry.z = carry.z*d + cur.z;
        carry.w = carry.w*d + cur.w;
    }
}

// ================= K5: off-diag + gate + RMSnorm + out_proj (both dirs) ======
#define OUT_SMEM (47168*4)
__global__ __launch_bounds__(256) void k_out(
    const float* __restrict__ Al_f, const float* __restrict__ Al_b,
    const float* __restrict__ D_f,  const float* __restrict__ D_b,
    const float* __restrict__ nw_f, const float* __restrict__ nw_b,
    const float* __restrict__ Wo_f, const float* __restrict__ Wo_b,
    float* __restrict__ out)
{
    extern __shared__ float sm[];
    float (*sPrevT)[260] = (float(*)[260])sm;                       // [n][h*64+p]
    float (*sY)[260]     = (float(*)[260])(sm + 16640);
    float (*sC)[68]      = (float(*)[68])(sm + 33280);
    float (*sWo)[68]     = (float(*)[68])(sm + 37632);
    float (*sdt)[4]      = (float(*)[4])(sm + 46336);
    float (*sAcs)[64]    = (float(*)[64])(sm + 46592);
    float (*sE)[64]      = (float(*)[64])(sm + 46848);
    float *sScale        = sm + 47104;

    int c = blockIdx.x, b = blockIdx.y;
    int tid = threadIdx.x;
    float accO[4][8] = {};

    for (int d = 0; d < 2; d++) {
        int cc = d ? (NC - 1 - c) : c;
        int base = b*SEQL + cc*CH;
        const float* Alog = d ? Al_b : Al_f;
        const float* Dp   = d ? D_b  : D_f;
        const float* nw   = d ? nw_b : nw_f;
        const float* Wo   = d ? Wo_b : Wo_f;
        const float* gx   = g_xbc[d];

        __syncthreads();
        { int l = tid >> 2, h = tid & 3; sdt[l][h] = g_dt[d][base*NH + tid]; }
        __syncthreads();
        if (tid < 4) {
            float A = -__expf(Alog[tid]);
            float run = 0.f;
            for (int l = 0; l < 64; l++) { run += sdt[l][tid] * A; sAcs[tid][l] = run; }
        }
        __syncthreads();
        { int h = tid >> 6, l = tid & 63; sE[h][l] = __expf(sAcs[h][l]); }
        #pragma unroll
        for (int it = 0; it < 4; it++) {
            int q = tid + it*256;
            int row = q >> 4, nq = (q & 15) * 4;
            *(float4*)&sC[row][nq] = *(const float4*)&gx[(base+row)*DX + DI + DS + nq];
        }
        {
            int pbase = (b*NC + cc)*NH*4096;
            #pragma unroll
            for (int it = 0; it < 16; it++) {
                int q = tid + it*256;
                int row = q >> 4, pq = (q & 15) * 4;
                float4 v = *(const float4*)&g_st[d][pbase + row*64 + pq];
                *(float4*)&sPrevT[row & 63][(row >> 6)*64 + pq] = v;
            }
        }
        __syncthreads();

        {
            int tl = tid >> 4, hq = tid & 15;
            float4 acc[4][4] = {};
            for (int n = 0; n < 64; n++) {
                float cv0 = sC[tl*4+0][n], cv1 = sC[tl*4+1][n];
                float cv2 = sC[tl*4+2][n], cv3 = sC[tl*4+3][n];
                #pragma unroll
                for (int j = 0; j < 4; j++) {
                    float4 p4 = *(float4*)&sPrevT[n][j*64 + hq*4];
                    fma4(acc[0][j], cv0, p4);
                    fma4(acc[1][j], cv1, p4);
                    fma4(acc[2][j], cv2, p4);
                    fma4(acc[3][j], cv3, p4);
                }
            }
            #pragma unroll
            for (int i = 0; i < 4; i++) {
                int l = tl*4 + i;
                int row = base + l;
                #pragma unroll
                for (int j = 0; j < 4; j++) {
                    int col = j*64 + hq*4;
                    float4 yd = *(const float4*)&g_yd[d][row*DI + col];
                    float4 xs = *(const float4*)&gx[row*DX + col];
                    float4 z4 = *(const float4*)&g_z[d][row*DI + col];
                    float e = sE[j][l], Dv = Dp[j];
                    float4 y;
                    y.x = (yd.x + e*acc[i][j].x + Dv*xs.x) * siluf(z4.x);
                    y.y = (yd.y + e*acc[i][j].y + Dv*xs.y) * siluf(z4.y);
                    y.z = (yd.z + e*acc[i][j].z + Dv*xs.z) * siluf(z4.z);
                    y.w = (yd.w + e*acc[i][j].w + Dv*xs.w) * siluf(z4.w);
                    *(float4*)&sY[l][col] = y;
                }
            }
        }
        __syncthreads();

        {
            int lr = tid >> 2, part = tid & 3;
            float s = 0.f;
            #pragma unroll
            for (int q = 0; q < 16; q++) {
                float4 v = *(float4*)&sY[lr][part*64 + q*4];
                s += dot4(v, v);
            }
            s += __shfl_xor_sync(0xffffffff, s, 1);
            s += __shfl_xor_sync(0xffffffff, s, 2);
            float scale = rsqrtf(s * (1.f/256.f) + 1e-5f);
            if (part == 0) sScale[lr] = scale;
            #pragma unroll
            for (int q = 0; q < 16; q++) {
                int col = part*64 + q*4;
                float4 v = *(float4*)&sY[lr][col];
                float4 w = *(const float4*)&nw[col];
                v.x *= scale*w.x; v.y *= scale*w.y; v.z *= scale*w.z; v.w *= scale*w.w;
                *(float4*)&sY[lr][col] = v;
            }
        }
        __syncthreads();

        {
            int tl2 = tid & 15, tk = tid >> 4;
            for (int jc = 0; jc < 4; jc++) {
                #pragma unroll
                for (int it = 0; it < 8; it++) {
                    int q = tid + it*256;
                    int row = q >> 4, jq = (q & 15) * 4;
                    *(float4*)&sWo[row][jq] = *(const float4*)&Wo[row*256 + jc*64 + jq];
                }
                __syncthreads();
                #pragma unroll
                for (int j4 = 0; j4 < 16; j4++) {
                    float4 y4[4];
                    #pragma unroll
                    for (int i = 0; i < 4; i++) {
                        int l = tl2*4 + i;
                        int lsrc = d ? (63 - l) : l;
                        y4[i] = *(float4*)&sY[lsrc][jc*64 + j4*4];
                    }
                    #pragma unroll
                    for (int kk = 0; kk < 8; kk++) {
                        float4 w4 = *(float4*)&sWo[tk*8 + kk][j4*4];
                        #pragma unroll
                        for (int i = 0; i < 4; i++) accO[i][kk] += dot4(y4[i], w4);
                    }
                }
                __syncthreads();
            }
        }
    }
    {
        int tl2 = tid & 15, tk = tid >> 4;
        #pragma unroll
        for (int i = 0; i < 4; i++) {
            int t = c*CH + tl2*4 + i;
            float4 v0 = make_float4(accO[i][0], accO[i][1], accO[i][2], accO[i][3]);
            float4 v1 = make_float4(accO[i][4], accO[i][5], accO[i][6], accO[i][7]);
            *(float4*)&out[(b*SEQL + t)*DM + tk*8 + 0] = v0;
            *(float4*)&out[(b*SEQL + t)*DM + tk*8 + 4] = v1;
        }
    }
}

extern "C" void kernel_launch(void* const* d_in, const int* in_sizes, int n_in,
                              void* d_out, int out_size)
{
    const float* x    = (const float*)d_in[0];
    const float* Wi_f = (const float*)d_in[1];
    const float* cw_f = (const float*)d_in[2];
    const float* cb_f = (const float*)d_in[3];
    const float* db_f = (const float*)d_in[4];
    const float* Al_f = (const float*)d_in[5];
    const float* D_f  = (const float*)d_in[6];
    const float* nw_f = (const float*)d_in[7];
    const float* Wo_f = (const float*)d_in[8];
    const float* Wi_b = (const float*)d_in[9];
    const float* cw_b = (const float*)d_in[10];
    const float* cb_b = (const float*)d_in[11];
    const float* db_b = (const float*)d_in[12];
    const float* Al_b = (const float*)d_in[13];
    const float* D_b  = (const float*)d_in[14];
    const float* nw_b = (const float*)d_in[15];
    const float* Wo_b = (const float*)d_in[16];
    float* out = (float*)d_out;

    cudaFuncSetAttribute(k_inproj, cudaFuncAttributeMaxDynamicSharedMemorySize, IP_SMEM);
    cudaFuncSetAttribute(k_chunk,  cudaFuncAttributeMaxDynamicSharedMemorySize, CH_SMEM);
    cudaFuncSetAttribute(k_out,    cudaFuncAttributeMaxDynamicSharedMemorySize, OUT_SMEM);

    dim3 g1(BL/128, (NPROJ + 63)/64, 2);
    k_inproj<<<g1, 256, IP_SMEM>>>(x, Wi_f, Wi_b, db_f, db_b);

    dim3 g2((BL*DX/4 + 255)/256, 2);
    k_conv<<<g2, 256>>>(cw_f, cb_f, cw_b, cb_b);

    dim3 g3(NC, BATCH, 2);
    k_chunk<<<g3, 256, CH_SMEM>>>(Al_f, Al_b);

    dim3 g4(4, BATCH*NH, 2);
    k_scan<<<g4, 256>>>();

    dim3 g5(NC, BATCH);
    k_out<<<g5, 256, OUT_SMEM>>>(Al_f, Al_b, D_f, D_b, nw_f, nw_b, Wo_f, Wo_b, out);
}

// round 5
// speedup vs baseline: 15.3019x; 1.3103x over previous
#include <cuda_runtime.h>
#include <math.h>

#define BATCH 16
#define SEQL  2048
#define BL    (BATCH*SEQL)      // 32768
#define DM    128
#define DI    256
#define DX    384
#define NH    4
#define HD    64
#define DS    64
#define CH    64
#define NC    32
#define NPROJ 644

// ---------------- scratch ----------------------------------------------------
__device__ float g_z[2][BL*DI];
__device__ float g_xbc0[2][BL*DX];
__device__ float g_xbc[2][BL*DX];
__device__ float g_dt[2][BL*NH];
__device__ float g_st[2][BATCH*NC*NH*HD*DS];   // per h: [p][n]
__device__ float g_yd[2][BL*DI];
__device__ float g_cd[2][BATCH*NH*NC];

__device__ __forceinline__ float softplusf(float x){ return x > 20.f ? x : log1pf(__expf(x)); }
__device__ __forceinline__ float siluf(float x){ return x / (1.f + __expf(-x)); }
__device__ __forceinline__ float dot4(float4 a, float4 b){
    return a.x*b.x + a.y*b.y + a.z*b.z + a.w*b.w;
}
__device__ __forceinline__ void fma4(float4& acc, float s, float4 v){
    acc.x += s*v.x; acc.y += s*v.y; acc.z += s*v.z; acc.w += s*v.w;
}
__device__ __forceinline__ float f2tf32(float x){
    unsigned r;
    asm("cvt.rna.tf32.f32 %0, %1;" : "=r"(r) : "f"(x));
    return __uint_as_float(r);
}
__device__ __forceinline__ void mma_tf32(float c[4],
    unsigned a0, unsigned a1, unsigned a2, unsigned a3,
    unsigned b0, unsigned b1)
{
    asm("mma.sync.aligned.m16n8k8.row.col.f32.tf32.tf32.f32 "
        "{%0,%1,%2,%3}, {%4,%5,%6,%7}, {%8,%9}, {%0,%1,%2,%3};"
        : "+f"(c[0]), "+f"(c[1]), "+f"(c[2]), "+f"(c[3])
        : "r"(a0), "r"(a1), "r"(a2), "r"(a3), "r"(b0), "r"(b1));
}

// ================= K1: in_proj GEMM via tf32 MMA =============================
#define IP_SMEM ((128*68 + 64*68)*4)

__device__ __forceinline__ void ip_store2(int dir, const float* db, int m, int c,
                                          float v0, float v1)
{
    if (c < DI) {
        float2 v = make_float2(v0, v1);
        *(float2*)&g_z[dir][m*DI + c] = v;
    } else if (c < DI + DX) {
        float2 v = make_float2(v0, v1);
        *(float2*)&g_xbc0[dir][m*DX + (c - DI)] = v;
    } else if (c < DI + DX + NH) {
        int h = c - DI - DX;
        g_dt[dir][m*NH + h]     = softplusf(v0 + db[h]);
        g_dt[dir][m*NH + h + 1] = softplusf(v1 + db[h + 1]);
    }
}

__global__ __launch_bounds__(256) void k_inproj(
    const float* __restrict__ x,
    const float* __restrict__ Wi_f, const float* __restrict__ Wi_b,
    const float* __restrict__ db_f, const float* __restrict__ db_b)
{
    extern __shared__ float sm[];
    float (*sX)[68] = (float(*)[68])sm;            // [128][68] tf32
    float (*sW)[68] = (float(*)[68])(sm + 128*68); // [64][68]  tf32
    int dir = blockIdx.z;
    const float* Wi = dir ? Wi_b : Wi_f;
    const float* db = dir ? db_b : db_f;
    int tid = threadIdx.x;
    int m0 = blockIdx.x * 128;
    int n0 = blockIdx.y * 64;
    int wid = tid >> 5, lane = tid & 31;
    int wm = wid & 1, wn = wid >> 1;
    int gid = lane >> 2, tig = lane & 3;
    float acc[4][2][4] = {};

    for (int kk = 0; kk < 2; kk++) {
        #pragma unroll
        for (int it = 0; it < 8; it++) {
            int q = tid + it*256;
            int row = q >> 4, kq = (q & 15) * 4;
            int m = m0 + row;
            int xr = dir ? ((m & ~2047) + 2047 - (m & 2047)) : m;
            float4 v = *(const float4*)&x[xr*128 + kk*64 + kq];
            sX[row][kq+0] = f2tf32(v.x); sX[row][kq+1] = f2tf32(v.y);
            sX[row][kq+2] = f2tf32(v.z); sX[row][kq+3] = f2tf32(v.w);
        }
        #pragma unroll
        for (int it = 0; it < 4; it++) {
            int q = tid + it*256;
            int row = q >> 4, kq = (q & 15) * 4;
            int n = n0 + row;
            float4 v = make_float4(0.f,0.f,0.f,0.f);
            if (n < NPROJ) v = *(const float4*)&Wi[n*128 + kk*64 + kq];
            sW[row][kq+0] = f2tf32(v.x); sW[row][kq+1] = f2tf32(v.y);
            sW[row][kq+2] = f2tf32(v.z); sW[row][kq+3] = f2tf32(v.w);
        }
        __syncthreads();
        #pragma unroll
        for (int ks = 0; ks < 8; ks++) {
            int kb = ks*8;
            unsigned b[2][2];
            #pragma unroll
            for (int ni = 0; ni < 2; ni++) {
                int n = wn*16 + ni*8 + gid;
                b[ni][0] = __float_as_uint(sW[n][kb + tig]);
                b[ni][1] = __float_as_uint(sW[n][kb + tig + 4]);
            }
            #pragma unroll
            for (int mi = 0; mi < 4; mi++) {
                int r = wm*64 + mi*16 + gid;
                unsigned a0 = __float_as_uint(sX[r    ][kb + tig]);
                unsigned a1 = __float_as_uint(sX[r + 8][kb + tig]);
                unsigned a2 = __float_as_uint(sX[r    ][kb + tig + 4]);
                unsigned a3 = __float_as_uint(sX[r + 8][kb + tig + 4]);
                mma_tf32(acc[mi][0], a0, a1, a2, a3, b[0][0], b[0][1]);
                mma_tf32(acc[mi][1], a0, a1, a2, a3, b[1][0], b[1][1]);
            }
        }
        __syncthreads();
    }
    #pragma unroll
    for (int mi = 0; mi < 4; mi++) {
        int r0 = m0 + wm*64 + mi*16 + gid;
        #pragma unroll
        for (int ni = 0; ni < 2; ni++) {
            int c = n0 + wn*16 + ni*8 + tig*2;
            ip_store2(dir, db, r0,     c, acc[mi][ni][0], acc[mi][ni][1]);
            ip_store2(dir, db, r0 + 8, c, acc[mi][ni][2], acc[mi][ni][3]);
        }
    }
}

// ================= K2: causal depthwise conv(4) + bias + silu (float4) =======
__global__ void k_conv(const float* __restrict__ cw_f, const float* __restrict__ cb_f,
                       const float* __restrict__ cw_b, const float* __restrict__ cb_b)
{
    int dir = blockIdx.y;
    const float* cw = dir ? cw_b : cw_f;
    const float* cb = dir ? cb_b : cb_f;
    int idx = blockIdx.x * 256 + threadIdx.x;
    if (idx >= BL * DX / 4) return;
    int m = idx / (DX/4);
    int j = (idx - m * (DX/4)) * 4;
    int t = m & 2047;
    float4 acc = *(const float4*)&cb[j];
    float w[4][4];
    #pragma unroll
    for (int c = 0; c < 4; c++) {
        float4 wv = *(const float4*)&cw[(j + c) * 4];
        w[c][0] = wv.x; w[c][1] = wv.y; w[c][2] = wv.z; w[c][3] = wv.w;
    }
    #pragma unroll
    for (int k = 0; k < 4; k++) {
        int tt = t - 3 + k;
        if (tt >= 0) {
            float4 v = *(const float4*)&g_xbc0[dir][(m - 3 + k)*DX + j];
            acc.x += v.x * w[0][k];
            acc.y += v.y * w[1][k];
            acc.z += v.z * w[2][k];
            acc.w += v.w * w[3][k];
        }
    }
    acc.x = siluf(acc.x); acc.y = siluf(acc.y); acc.z = siluf(acc.z); acc.w = siluf(acc.w);
    *(float4*)&g_xbc[dir][m*DX + j] = acc;
}

// ================= K3: per-chunk diagonal block + chunk state ================
#define CH_SMEM (25920*4)
__global__ __launch_bounds__(256) void k_chunk(const float* __restrict__ Al_f,
                                               const float* __restrict__ Al_b)
{
    extern __shared__ float sm[];
    float (*sB)[68]   = (float(*)[68])sm;
    float (*sW)[68]   = (float(*)[68])(sm + 64*68);           // C, then W per head
    float (*sX)[260]  = (float(*)[260])(sm + 2*64*68);
    float (*sdt)[4]   = (float(*)[4])(sm + 2*64*68 + 64*260);
    float (*sAcs)[64] = (float(*)[64])(sm + 2*64*68 + 64*260 + 256);
    float *sdec       = sm + 2*64*68 + 64*260 + 512;

    int c = blockIdx.x, b = blockIdx.y, dir = blockIdx.z;
    const float* gx = g_xbc[dir];
    int tid = threadIdx.x;
    int base = b*SEQL + c*CH;

    { int l = tid >> 2, h = tid & 3; sdt[l][h] = g_dt[dir][base*NH + tid]; }
    #pragma unroll
    for (int it = 0; it < 4; it++) {
        int q = tid + it*256;
        int row = q >> 4, nq = (q & 15) * 4;
        *(float4*)&sB[row][nq] = *(const float4*)&gx[(base+row)*DX + DI + nq];
        *(float4*)&sW[row][nq] = *(const float4*)&gx[(base+row)*DX + DI + DS + nq]; // C
    }
    __syncthreads();
    #pragma unroll
    for (int it = 0; it < 16; it++) {
        int q = tid + it*256;
        int row = q >> 6, qq = (q & 63) * 4;
        float4 v = *(const float4*)&gx[(base+row)*DX + qq];
        float dtv = sdt[row][qq >> 6];
        v.x *= dtv; v.y *= dtv; v.z *= dtv; v.w *= dtv;
        *(float4*)&sX[row][qq] = v;
    }
    if (tid < 4) {
        float A = -__expf((dir ? Al_b : Al_f)[tid]);
        float run = 0.f;
        for (int l = 0; l < 64; l++) { run += sdt[l][tid] * A; sAcs[tid][l] = run; }
    }
    __syncthreads();

    int ts = tid & 15, tl = tid >> 4;
    float cb[4][4] = {};
    if (ts <= tl) {
        #pragma unroll
        for (int nq = 0; nq < 16; nq++) {
            float4 a4[4], b4[4];
            #pragma unroll
            for (int i = 0; i < 4; i++) a4[i] = *(float4*)&sW[tl*4 + i][nq*4];
            #pragma unroll
            for (int j = 0; j < 4; j++) b4[j] = *(float4*)&sB[ts*4 + j][nq*4];
            #pragma unroll
            for (int i = 0; i < 4; i++)
                #pragma unroll
                for (int j = 0; j < 4; j++) cb[i][j] += dot4(a4[i], b4[j]);
        }
    }
    __syncthreads();

    int sbase = (b*NC + c)*NH*4096;
    for (int h = 0; h < NH; h++) {
        #pragma unroll
        for (int i = 0; i < 4; i++) {
            int l = tl*4 + i;
            float al = sAcs[h][l];
            float4 w;
            w.x = (ts*4+0 <= l) ? cb[i][0] * __expf(al - sAcs[h][ts*4+0]) : 0.f;
            w.y = (ts*4+1 <= l) ? cb[i][1] * __expf(al - sAcs[h][ts*4+1]) : 0.f;
            w.z = (ts*4+2 <= l) ? cb[i][2] * __expf(al - sAcs[h][ts*4+2]) : 0.f;
            w.w = (ts*4+3 <= l) ? cb[i][3] * __expf(al - sAcs[h][ts*4+3]) : 0.f;
            *(float4*)&sW[l][ts*4] = w;
        }
        if (tid < 64) sdec[tid] = __expf(sAcs[h][63] - sAcs[h][tid]);
        __syncthreads();

        // Y_diag
        {
            float4 acc[4] = {};
            for (int sq = 0; sq <= tl; sq++) {
                float4 x0 = *(float4*)&sX[sq*4+0][h*64 + ts*4];
                float4 x1 = *(float4*)&sX[sq*4+1][h*64 + ts*4];
                float4 x2 = *(float4*)&sX[sq*4+2][h*64 + ts*4];
                float4 x3 = *(float4*)&sX[sq*4+3][h*64 + ts*4];
                #pragma unroll
                for (int i = 0; i < 4; i++) {
                    float4 w4 = *(float4*)&sW[tl*4 + i][sq*4];
                    fma4(acc[i], w4.x, x0);
                    fma4(acc[i], w4.y, x1);
                    fma4(acc[i], w4.z, x2);
                    fma4(acc[i], w4.w, x3);
                }
            }
            #pragma unroll
            for (int i = 0; i < 4; i++)
                *(float4*)&g_yd[dir][(base + tl*4 + i)*DI + h*64 + ts*4] = acc[i];
        }
        // chunk state st[p][n] — stored DIRECT (row p, col n)
        {
            float st[4][4] = {};   // [p][n]
            for (int l = 0; l < 64; l++) {
                float d = sdec[l];
                float4 x4 = *(float4*)&sX[l][h*64 + tl*4];
                float4 b4 = *(float4*)&sB[l][ts*4];
                x4.x *= d; x4.y *= d; x4.z *= d; x4.w *= d;
                st[0][0] += x4.x*b4.x; st[0][1] += x4.x*b4.y; st[0][2] += x4.x*b4.z; st[0][3] += x4.x*b4.w;
                st[1][0] += x4.y*b4.x; st[1][1] += x4.y*b4.y; st[1][2] += x4.y*b4.z; st[1][3] += x4.y*b4.w;
                st[2][0] += x4.z*b4.x; st[2][1] += x4.z*b4.y; st[2][2] += x4.z*b4.z; st[2][3] += x4.z*b4.w;
                st[3][0] += x4.w*b4.x; st[3][1] += x4.w*b4.y; st[3][2] += x4.w*b4.z; st[3][3] += x4.w*b4.w;
            }
            #pragma unroll
            for (int i = 0; i < 4; i++) {
                float4 v = make_float4(st[i][0], st[i][1], st[i][2], st[i][3]);
                *(float4*)&g_st[dir][sbase + h*4096 + (tl*4 + i)*64 + ts*4] = v;
            }
        }
        if (tid == 0) g_cd[dir][(b*NH + h)*NC + c] = __expf(sAcs[h][63]);
        __syncthreads();
    }
}

// ================= K4: inter-chunk scan — pipelined, vectorized ==============
__global__ __launch_bounds__(256) void k_scan()
{
    int grp = blockIdx.x;
    int bh  = blockIdx.y;
    int dir = blockIdx.z;
    int h = bh & 3, b = bh >> 2;
    int tid = threadIdx.x;
    int e0 = grp*1024 + tid*4;

    float cd[NC];
    #pragma unroll
    for (int c = 0; c < NC; c++) cd[c] = g_cd[dir][(b*NH + h)*NC + c];

    float* p = &g_st[dir][(b*NC*NH + h)*4096 + e0];
    const int cstride = NH*4096;

    float4 carry = make_float4(0.f, 0.f, 0.f, 0.f);
    float4 nxt = *(float4*)p;
    #pragma unroll
    for (int c = 0; c < NC; c++) {
        float4 cur = nxt;
        if (c + 1 < NC) nxt = *(float4*)(p + (c+1)*cstride);
        *(float4*)(p + c*cstride) = carry;
        float d = cd[c];
        carry.x = carry.x*d + cur.x;
        carry.y = carry.y*d + cur.y;
        carry.z = carry.z*d + cur.z;
        carry.w = carry.w*d + cur.w;
    }
}

// ================= K5: off-diag + gate + RMSnorm + out_proj via tf32 MMA =====
// smem floats: sPrev[256][68] (alias sWo[128][68]) | sY[64][260] | sC[64][68]
//              | sdt 256 | sAcs 256 | sE 256   => 39168 floats
#define OUT_SMEM (39168*4)
__global__ __launch_bounds__(256) void k_out(
    const float* __restrict__ Al_f, const float* __restrict__ Al_b,
    const float* __restrict__ D_f,  const float* __restrict__ D_b,
    const float* __restrict__ nw_f, const float* __restrict__ nw_b,
    const float* __restrict__ Wo_f, const float* __restrict__ Wo_b,
    float* __restrict__ out)
{
    extern __shared__ float sm[];
    float (*sPrev)[68] = (float(*)[68])sm;            // [hp=256][n=64] tf32
    float (*sWo)[68]   = (float(*)[68])sm;            // alias: [kout=128][j=64] tf32
    float (*sY)[260]   = (float(*)[260])(sm + 17408); // [l=64][q=256] tf32 after RMS
    float (*sC)[68]    = (float(*)[68])(sm + 34048);  // [l=64][n=64] tf32
    float (*sdt)[4]    = (float(*)[4])(sm + 38400);
    float (*sAcs)[64]  = (float(*)[64])(sm + 38656);
    float (*sE)[64]    = (float(*)[64])(sm + 38912);

    int c = blockIdx.x, b = blockIdx.y;
    int tid = threadIdx.x;
    int wid = tid >> 5, lane = tid & 31;
    int gid = lane >> 2, tig = lane & 3;

    float oacc[8][4] = {};   // out_proj accumulators, persist across jc and dirs

    for (int d = 0; d < 2; d++) {
        int cc = d ? (NC - 1 - c) : c;
        int base = b*SEQL + cc*CH;
        const float* Alog = d ? Al_b : Al_f;
        const float* Dp   = d ? D_b  : D_f;
        const float* nw   = d ? nw_b : nw_f;
        const float* Wo   = d ? Wo_b : Wo_f;
        const float* gx   = g_xbc[d];

        __syncthreads();
        { int l = tid >> 2, h = tid & 3; sdt[l][h] = g_dt[d][base*NH + tid]; }
        __syncthreads();
        if (tid < 4) {
            float A = -__expf(Alog[tid]);
            float run = 0.f;
            for (int l = 0; l < 64; l++) { run += sdt[l][tid] * A; sAcs[tid][l] = run; }
        }
        __syncthreads();
        { int h = tid >> 6, l = tid & 63; sE[h][l] = __expf(sAcs[h][l]); }
        // load C (tf32)
        #pragma unroll
        for (int it = 0; it < 4; it++) {
            int q = tid + it*256;
            int row = q >> 4, nq = (q & 15) * 4;
            float4 v = *(const float4*)&gx[(base+row)*DX + DI + DS + nq];
            sC[row][nq+0] = f2tf32(v.x); sC[row][nq+1] = f2tf32(v.y);
            sC[row][nq+2] = f2tf32(v.z); sC[row][nq+3] = f2tf32(v.w);
        }
        // load prev states (tf32): row hp = h*64+p, col n
        {
            int pbase = (b*NC + cc)*NH*4096;
            #pragma unroll
            for (int it = 0; it < 16; it++) {
                int q = tid + it*256;
                int row = q >> 4, nq = (q & 15) * 4;
                float4 v = *(const float4*)&g_st[d][pbase + row*64 + nq];
                sPrev[row][nq+0] = f2tf32(v.x); sPrev[row][nq+1] = f2tf32(v.y);
                sPrev[row][nq+2] = f2tf32(v.z); sPrev[row][nq+3] = f2tf32(v.w);
            }
        }
        __syncthreads();

        // ---- off-diag: Yo[l][hp] = sum_n C[l][n] * prev[hp][n] ----
        {
            int wn = wid;                 // n-range: wn*32 .. +32 (4 n-tiles)
            float facc[4][4][4] = {};     // [mtile][ntile][frag]
            #pragma unroll
            for (int ks = 0; ks < 8; ks++) {
                int kb = ks*8;
                unsigned bf[4][2];
                #pragma unroll
                for (int nt = 0; nt < 4; nt++) {
                    int r = wn*32 + nt*8 + gid;
                    bf[nt][0] = __float_as_uint(sPrev[r][kb + tig]);
                    bf[nt][1] = __float_as_uint(sPrev[r][kb + tig + 4]);
                }
                #pragma unroll
                for (int mt = 0; mt < 4; mt++) {
                    int r = mt*16 + gid;
                    unsigned a0 = __float_as_uint(sC[r    ][kb + tig]);
                    unsigned a1 = __float_as_uint(sC[r + 8][kb + tig]);
                    unsigned a2 = __float_as_uint(sC[r    ][kb + tig + 4]);
                    unsigned a3 = __float_as_uint(sC[r + 8][kb + tig + 4]);
                    #pragma unroll
                    for (int nt = 0; nt < 4; nt++)
                        mma_tf32(facc[mt][nt], a0, a1, a2, a3, bf[nt][0], bf[nt][1]);
                }
            }
            // epilogue: combine + gate, store to sY with l-flip for d=1
            #pragma unroll
            for (int mt = 0; mt < 4; mt++) {
                #pragma unroll
                for (int nt = 0; nt < 4; nt++) {
                    int q = wn*32 + nt*8 + tig*2;
                    int h = q >> 6;
                    float Dv = Dp[h];
                    #pragma unroll
                    for (int half = 0; half < 2; half++) {
                        int l = mt*16 + gid + half*8;
                        int row = base + l;
                        float e = sE[h][l];
                        float2 yd = *(const float2*)&g_yd[d][row*DI + q];
                        float2 xs = *(const float2*)&gx[row*DX + q];
                        float2 z2 = *(const float2*)&g_z[d][row*DI + q];
                        float v0 = facc[mt][nt][half*2 + 0];
                        float v1 = facc[mt][nt][half*2 + 1];
                        float y0 = (yd.x + e*v0 + Dv*xs.x) * siluf(z2.x);
                        float y1 = (yd.y + e*v1 + Dv*xs.y) * siluf(z2.y);
                        int srow = d ? (63 - l) : l;
                        *(float2*)&sY[srow][q] = make_float2(y0, y1);
                    }
                }
            }
        }
        __syncthreads();

        // ---- RMS norm per row (4 threads/row), re-quantize to tf32 ----
        {
            int lr = tid >> 2, part = tid & 3;
            float s = 0.f;
            #pragma unroll
            for (int q = 0; q < 16; q++) {
                float4 v = *(float4*)&sY[lr][part*64 + q*4];
                s += dot4(v, v);
            }
            s += __shfl_xor_sync(0xffffffff, s, 1);
            s += __shfl_xor_sync(0xffffffff, s, 2);
            float scale = rsqrtf(s * (1.f/256.f) + 1e-5f);
            #pragma unroll
            for (int q = 0; q < 16; q++) {
                int col = part*64 + q*4;
                float4 v = *(float4*)&sY[lr][col];
                float4 w = *(const float4*)&nw[col];
                v.x = f2tf32(v.x * scale * w.x);
                v.y = f2tf32(v.y * scale * w.y);
                v.z = f2tf32(v.z * scale * w.z);
                v.w = f2tf32(v.w * scale * w.w);
                *(float4*)&sY[lr][col] = v;
            }
        }
        __syncthreads();

        // ---- out_proj: out[r][kout] += sum_j Y[r][j] * Wo[kout][j] ----
        {
            int wm = wid & 3, wn2 = wid >> 2;
            for (int jc = 0; jc < 4; jc++) {
                #pragma unroll
                for (int it = 0; it < 8; it++) {
                    int q = tid + it*256;
                    int row = q >> 4, jq = (q & 15) * 4;
                    float4 v = *(const float4*)&Wo[row*256 + jc*64 + jq];
                    sWo[row][jq+0] = f2tf32(v.x); sWo[row][jq+1] = f2tf32(v.y);
                    sWo[row][jq+2] = f2tf32(v.z); sWo[row][jq+3] = f2tf32(v.w);
                }
                __syncthreads();
                #pragma unroll
                for (int ks = 0; ks < 8; ks++) {
                    int kb = ks*8;
                    int ar = wm*16 + gid;
                    unsigned a0 = __float_as_uint(sY[ar    ][jc*64 + kb + tig]);
                    unsigned a1 = __float_as_uint(sY[ar + 8][jc*64 + kb + tig]);
                    unsigned a2 = __float_as_uint(sY[ar    ][jc*64 + kb + tig + 4]);
                    unsigned a3 = __float_as_uint(sY[ar + 8][jc*64 + kb + tig + 4]);
                    #pragma unroll
                    for (int nt = 0; nt < 8; nt++) {
                        int r = wn2*64 + nt*8 + gid;
                        unsigned b0 = __float_as_uint(sWo[r][kb + tig]);
                        unsigned b1 = __float_as_uint(sWo[r][kb + tig + 4]);
                        mma_tf32(oacc[nt], a0, a1, a2, a3, b0, b1);
                    }
                }
                __syncthreads();
            }
        }
    }

    // ---- final store: rows t = c*CH + r (dirs already combined) ----
    {
        int wm = wid & 3, wn2 = wid >> 2;
        #pragma unroll
        for (int nt = 0; nt < 8; nt++) {
            int kout = wn2*64 + nt*8 + tig*2;
            #pragma unroll
            for (int half = 0; half < 2; half++) {
                int r = wm*16 + gid + half*8;
                int t = c*CH + r;
                *(float2*)&out[(b*SEQL + t)*DM + kout] =
                    make_float2(oacc[nt][half*2], oacc[nt][half*2 + 1]);
            }
        }
    }
}

extern "C" void kernel_launch(void* const* d_in, const int* in_sizes, int n_in,
                              void* d_out, int out_size)
{
    const float* x    = (const float*)d_in[0];
    const float* Wi_f = (const float*)d_in[1];
    const float* cw_f = (const float*)d_in[2];
    const float* cb_f = (const float*)d_in[3];
    const float* db_f = (const float*)d_in[4];
    const float* Al_f = (const float*)d_in[5];
    const float* D_f  = (const float*)d_in[6];
    const float* nw_f = (const float*)d_in[7];
    const float* Wo_f = (const float*)d_in[8];
    const float* Wi_b = (const float*)d_in[9];
    const float* cw_b = (const float*)d_in[10];
    const float* cb_b = (const float*)d_in[11];
    const float* db_b = (const float*)d_in[12];
    const float* Al_b = (const float*)d_in[13];
    const float* D_b  = (const float*)d_in[14];
    const float* nw_b = (const float*)d_in[15];
    const float* Wo_b = (const float*)d_in[16];
    float* out = (float*)d_out;

    cudaFuncSetAttribute(k_inproj, cudaFuncAttributeMaxDynamicSharedMemorySize, IP_SMEM);
    cudaFuncSetAttribute(k_chunk,  cudaFuncAttributeMaxDynamicSharedMemorySize, CH_SMEM);
    cudaFuncSetAttribute(k_out,    cudaFuncAttributeMaxDynamicSharedMemorySize, OUT_SMEM);

    dim3 g1(BL/128, (NPROJ + 63)/64, 2);
    k_inproj<<<g1, 256, IP_SMEM>>>(x, Wi_f, Wi_b, db_f, db_b);

    dim3 g2((BL*DX/4 + 255)/256, 2);
    k_conv<<<g2, 256>>>(cw_f, cb_f, cw_b, cb_b);

    dim3 g3(NC, BATCH, 2);
    k_chunk<<<g3, 256, CH_SMEM>>>(Al_f, Al_b);

    dim3 g4(4, BATCH*NH, 2);
    k_scan<<<g4, 256>>>();

    dim3 g5(NC, BATCH);
    k_out<<<g5, 256, OUT_SMEM>>>(Al_f, Al_b, D_f, D_b, nw_f, nw_b, Wo_f, Wo_b, out);
}

// round 6
// speedup vs baseline: 15.8972x; 1.0389x over previous
#include <cuda_runtime.h>
#include <math.h>

#define BATCH 16
#define SEQL  2048
#define BL    (BATCH*SEQL)      // 32768
#define DM    128
#define DI    256
#define DX    384
#define NH    4
#define HD    64
#define DS    64
#define CH    64
#define NC    32
#define NPROJ 644

// ---------------- scratch ----------------------------------------------------
__device__ float g_z[2][BL*DI];
__device__ float g_xbc0[2][BL*DX];
__device__ float g_xbc[2][BL*DX];
__device__ float g_dt[2][BL*NH];
__device__ float g_st[2][BATCH*NC*NH*HD*DS];   // per h: [p][n]
__device__ float g_yd[2][BL*DI];
__device__ float g_cd[2][BATCH*NH*NC];

__device__ __forceinline__ float softplusf(float x){ return x > 20.f ? x : log1pf(__expf(x)); }
__device__ __forceinline__ float siluf(float x){ return x / (1.f + __expf(-x)); }
__device__ __forceinline__ float dot4(float4 a, float4 b){
    return a.x*b.x + a.y*b.y + a.z*b.z + a.w*b.w;
}
__device__ __forceinline__ float f2tf32(float x){
    unsigned r;
    asm("cvt.rna.tf32.f32 %0, %1;" : "=r"(r) : "f"(x));
    return __uint_as_float(r);
}
__device__ __forceinline__ void mma_tf32(float c[4],
    unsigned a0, unsigned a1, unsigned a2, unsigned a3,
    unsigned b0, unsigned b1)
{
    asm("mma.sync.aligned.m16n8k8.row.col.f32.tf32.tf32.f32 "
        "{%0,%1,%2,%3}, {%4,%5,%6,%7}, {%8,%9}, {%0,%1,%2,%3};"
        : "+f"(c[0]), "+f"(c[1]), "+f"(c[2]), "+f"(c[3])
        : "r"(a0), "r"(a1), "r"(a2), "r"(a3), "r"(b0), "r"(b1));
}

// ================= K1: in_proj GEMM via tf32 MMA =============================
#define IP_SMEM ((128*68 + 64*68)*4)

__device__ __forceinline__ void ip_store2(int dir, const float* db, int m, int c,
                                          float v0, float v1)
{
    if (c < DI) {
        float2 v = make_float2(v0, v1);
        *(float2*)&g_z[dir][m*DI + c] = v;
    } else if (c < DI + DX) {
        float2 v = make_float2(v0, v1);
        *(float2*)&g_xbc0[dir][m*DX + (c - DI)] = v;
    } else if (c < DI + DX + NH) {
        int h = c - DI - DX;
        g_dt[dir][m*NH + h]     = softplusf(v0 + db[h]);
        g_dt[dir][m*NH + h + 1] = softplusf(v1 + db[h + 1]);
    }
}

__global__ __launch_bounds__(256) void k_inproj(
    const float* __restrict__ x,
    const float* __restrict__ Wi_f, const float* __restrict__ Wi_b,
    const float* __restrict__ db_f, const float* __restrict__ db_b)
{
    extern __shared__ float sm[];
    float (*sX)[68] = (float(*)[68])sm;            // [128][68] tf32
    float (*sW)[68] = (float(*)[68])(sm + 128*68); // [64][68]  tf32
    int dir = blockIdx.z;
    const float* Wi = dir ? Wi_b : Wi_f;
    const float* db = dir ? db_b : db_f;
    int tid = threadIdx.x;
    int m0 = blockIdx.x * 128;
    int n0 = blockIdx.y * 64;
    int wid = tid >> 5, lane = tid & 31;
    int wm = wid & 1, wn = wid >> 1;
    int gid = lane >> 2, tig = lane & 3;
    float acc[4][2][4] = {};

    for (int kk = 0; kk < 2; kk++) {
        #pragma unroll
        for (int it = 0; it < 8; it++) {
            int q = tid + it*256;
            int row = q >> 4, kq = (q & 15) * 4;
            int m = m0 + row;
            int xr = dir ? ((m & ~2047) + 2047 - (m & 2047)) : m;
            float4 v = *(const float4*)&x[xr*128 + kk*64 + kq];
            sX[row][kq+0] = f2tf32(v.x); sX[row][kq+1] = f2tf32(v.y);
            sX[row][kq+2] = f2tf32(v.z); sX[row][kq+3] = f2tf32(v.w);
        }
        #pragma unroll
        for (int it = 0; it < 4; it++) {
            int q = tid + it*256;
            int row = q >> 4, kq = (q & 15) * 4;
            int n = n0 + row;
            float4 v = make_float4(0.f,0.f,0.f,0.f);
            if (n < NPROJ) v = *(const float4*)&Wi[n*128 + kk*64 + kq];
            sW[row][kq+0] = f2tf32(v.x); sW[row][kq+1] = f2tf32(v.y);
            sW[row][kq+2] = f2tf32(v.z); sW[row][kq+3] = f2tf32(v.w);
        }
        __syncthreads();
        #pragma unroll
        for (int ks = 0; ks < 8; ks++) {
            int kb = ks*8;
            unsigned b[2][2];
            #pragma unroll
            for (int ni = 0; ni < 2; ni++) {
                int n = wn*16 + ni*8 + gid;
                b[ni][0] = __float_as_uint(sW[n][kb + tig]);
                b[ni][1] = __float_as_uint(sW[n][kb + tig + 4]);
            }
            #pragma unroll
            for (int mi = 0; mi < 4; mi++) {
                int r = wm*64 + mi*16 + gid;
                unsigned a0 = __float_as_uint(sX[r    ][kb + tig]);
                unsigned a1 = __float_as_uint(sX[r + 8][kb + tig]);
                unsigned a2 = __float_as_uint(sX[r    ][kb + tig + 4]);
                unsigned a3 = __float_as_uint(sX[r + 8][kb + tig + 4]);
                mma_tf32(acc[mi][0], a0, a1, a2, a3, b[0][0], b[0][1]);
                mma_tf32(acc[mi][1], a0, a1, a2, a3, b[1][0], b[1][1]);
            }
        }
        __syncthreads();
    }
    #pragma unroll
    for (int mi = 0; mi < 4; mi++) {
        int r0 = m0 + wm*64 + mi*16 + gid;
        #pragma unroll
        for (int ni = 0; ni < 2; ni++) {
            int c = n0 + wn*16 + ni*8 + tig*2;
            ip_store2(dir, db, r0,     c, acc[mi][ni][0], acc[mi][ni][1]);
            ip_store2(dir, db, r0 + 8, c, acc[mi][ni][2], acc[mi][ni][3]);
        }
    }
}

// ================= K2: causal depthwise conv(4) + bias + silu (float4) =======
__global__ void k_conv(const float* __restrict__ cw_f, const float* __restrict__ cb_f,
                       const float* __restrict__ cw_b, const float* __restrict__ cb_b)
{
    int dir = blockIdx.y;
    const float* cw = dir ? cw_b : cw_f;
    const float* cb = dir ? cb_b : cb_f;
    int idx = blockIdx.x * 256 + threadIdx.x;
    if (idx >= BL * DX / 4) return;
    int m = idx / (DX/4);
    int j = (idx - m * (DX/4)) * 4;
    int t = m & 2047;
    float4 acc = *(const float4*)&cb[j];
    float w[4][4];
    #pragma unroll
    for (int c = 0; c < 4; c++) {
        float4 wv = *(const float4*)&cw[(j + c) * 4];
        w[c][0] = wv.x; w[c][1] = wv.y; w[c][2] = wv.z; w[c][3] = wv.w;
    }
    #pragma unroll
    for (int k = 0; k < 4; k++) {
        int tt = t - 3 + k;
        if (tt >= 0) {
            float4 v = *(const float4*)&g_xbc0[dir][(m - 3 + k)*DX + j];
            acc.x += v.x * w[0][k];
            acc.y += v.y * w[1][k];
            acc.z += v.z * w[2][k];
            acc.w += v.w * w[3][k];
        }
    }
    acc.x = siluf(acc.x); acc.y = siluf(acc.y); acc.z = siluf(acc.z); acc.w = siluf(acc.w);
    *(float4*)&g_xbc[dir][m*DX + j] = acc;
}

// ================= K3: per-chunk diagonal block + chunk state via tf32 MMA ===
// smem floats: sC 4352 | sB 4352 | sBT 4352 | sW 4352 | sXT [256][68] 17408 |
//              sdt 256 | sAcs 256 | sdec 64  => 35392 floats (141.5 KB)
#define CH_SMEM (35392*4)
__global__ __launch_bounds__(256) void k_chunk(const float* __restrict__ Al_f,
                                               const float* __restrict__ Al_b)
{
    extern __shared__ float sm[];
    float (*sC)[68]   = (float(*)[68])sm;
    float (*sB)[68]   = (float(*)[68])(sm + 4352);
    float (*sBT)[68]  = (float(*)[68])(sm + 8704);
    float (*sW)[68]   = (float(*)[68])(sm + 13056);
    float (*sXT)[68]  = (float(*)[68])(sm + 17408);   // [256 = h*64+p][s]
    float (*sdt)[4]   = (float(*)[4])(sm + 34816);
    float (*sAcs)[64] = (float(*)[64])(sm + 35072);
    float *sdec       = sm + 35328;

    int c = blockIdx.x, b = blockIdx.y, dir = blockIdx.z;
    const float* gx = g_xbc[dir];
    int tid = threadIdx.x;
    int base = b*SEQL + c*CH;
    int wid = tid >> 5, lane = tid & 31;
    int gid = lane >> 2, tig = lane & 3;
    int wm = wid & 1, wn = wid >> 1;      // 2(m) x 4(n) warp grid

    { int l = tid >> 2, h = tid & 3; sdt[l][h] = g_dt[dir][base*NH + tid]; }
    #pragma unroll
    for (int it = 0; it < 4; it++) {
        int q = tid + it*256;
        int row = q >> 4, nq = (q & 15) * 4;
        float4 vb = *(const float4*)&gx[(base+row)*DX + DI + nq];
        float4 vc = *(const float4*)&gx[(base+row)*DX + DI + DS + nq];
        sB[row][nq+0] = f2tf32(vb.x); sB[row][nq+1] = f2tf32(vb.y);
        sB[row][nq+2] = f2tf32(vb.z); sB[row][nq+3] = f2tf32(vb.w);
        sC[row][nq+0] = f2tf32(vc.x); sC[row][nq+1] = f2tf32(vc.y);
        sC[row][nq+2] = f2tf32(vc.z); sC[row][nq+3] = f2tf32(vc.w);
    }
    __syncthreads();
    // Xdt transposed: sXT[h*64+p][s] = x[s][h*64+p]*dt[s][h]  (tf32)
    #pragma unroll
    for (int it = 0; it < 16; it++) {
        int q = tid + it*256;
        int s = q >> 6, p4 = (q & 63) * 4;
        float4 v = *(const float4*)&gx[(base+s)*DX + p4];
        float dtv = sdt[s][p4 >> 6];
        sXT[p4+0][s] = f2tf32(v.x * dtv);
        sXT[p4+1][s] = f2tf32(v.y * dtv);
        sXT[p4+2][s] = f2tf32(v.z * dtv);
        sXT[p4+3][s] = f2tf32(v.w * dtv);
    }
    // B transposed (already tf32 in sB)
    #pragma unroll
    for (int it = 0; it < 16; it++) {
        int q = tid + it*256;
        int n = q >> 6, l = q & 63;
        sBT[n][l] = sB[l][n];
    }
    if (tid < 4) {
        float A = -__expf((dir ? Al_b : Al_f)[tid]);
        float run = 0.f;
        for (int l = 0; l < 64; l++) { run += sdt[l][tid] * A; sAcs[tid][l] = run; }
    }
    __syncthreads();

    // ---- phase 1: CB[l][s] = sum_n C[l][n]*B[s][n]  (fragments persist) ----
    float cbf[2][2][4] = {};
    #pragma unroll
    for (int ks = 0; ks < 8; ks++) {
        int kb = ks*8;
        unsigned bf[2][2];
        #pragma unroll
        for (int nt = 0; nt < 2; nt++) {
            int s = wn*16 + nt*8 + gid;
            bf[nt][0] = __float_as_uint(sB[s][kb + tig]);
            bf[nt][1] = __float_as_uint(sB[s][kb + tig + 4]);
        }
        #pragma unroll
        for (int mt = 0; mt < 2; mt++) {
            int r = wm*32 + mt*16 + gid;
            unsigned a0 = __float_as_uint(sC[r    ][kb + tig]);
            unsigned a1 = __float_as_uint(sC[r + 8][kb + tig]);
            unsigned a2 = __float_as_uint(sC[r    ][kb + tig + 4]);
            unsigned a3 = __float_as_uint(sC[r + 8][kb + tig + 4]);
            mma_tf32(cbf[mt][0], a0, a1, a2, a3, bf[0][0], bf[0][1]);
            mma_tf32(cbf[mt][1], a0, a1, a2, a3, bf[1][0], bf[1][1]);
        }
    }

    int sbase = (b*NC + c)*NH*4096;
    for (int h = 0; h < NH; h++) {
        __syncthreads();   // previous head done reading sW / sdec
        // ---- build W = mask(CB)*exp(Acs[l]-Acs[s]) in tf32, + sdec ----
        #pragma unroll
        for (int mt = 0; mt < 2; mt++) {
            #pragma unroll
            for (int half = 0; half < 2; half++) {
                int l = wm*32 + mt*16 + gid + half*8;
                float al = sAcs[h][l];
                #pragma unroll
                for (int nt = 0; nt < 2; nt++) {
                    int s0 = wn*16 + nt*8 + tig*2;
                    float v0 = (s0     <= l) ? cbf[mt][nt][half*2+0]*__expf(al - sAcs[h][s0])     : 0.f;
                    float v1 = (s0 + 1 <= l) ? cbf[mt][nt][half*2+1]*__expf(al - sAcs[h][s0 + 1]) : 0.f;
                    sW[l][s0]     = f2tf32(v0);
                    sW[l][s0 + 1] = f2tf32(v1);
                }
            }
        }
        if (tid < 64) sdec[tid] = __expf(sAcs[h][63] - sAcs[h][tid]);
        __syncthreads();

        // ---- phase 2: Ydiag[l][p] = sum_s W[l][s]*XdtT[p][s] ----
        {
            float f2[2][2][4] = {};
            #pragma unroll
            for (int ks = 0; ks < 8; ks++) {
                int kb = ks*8;
                unsigned bf[2][2];
                #pragma unroll
                for (int nt = 0; nt < 2; nt++) {
                    int p = wn*16 + nt*8 + gid;
                    bf[nt][0] = __float_as_uint(sXT[h*64 + p][kb + tig]);
                    bf[nt][1] = __float_as_uint(sXT[h*64 + p][kb + tig + 4]);
                }
                #pragma unroll
                for (int mt = 0; mt < 2; mt++) {
                    int r = wm*32 + mt*16 + gid;
                    unsigned a0 = __float_as_uint(sW[r    ][kb + tig]);
                    unsigned a1 = __float_as_uint(sW[r + 8][kb + tig]);
                    unsigned a2 = __float_as_uint(sW[r    ][kb + tig + 4]);
                    unsigned a3 = __float_as_uint(sW[r + 8][kb + tig + 4]);
                    mma_tf32(f2[mt][0], a0, a1, a2, a3, bf[0][0], bf[0][1]);
                    mma_tf32(f2[mt][1], a0, a1, a2, a3, bf[1][0], bf[1][1]);
                }
            }
            #pragma unroll
            for (int mt = 0; mt < 2; mt++) {
                #pragma unroll
                for (int half = 0; half < 2; half++) {
                    int l = wm*32 + mt*16 + gid + half*8;
                    #pragma unroll
                    for (int nt = 0; nt < 2; nt++) {
                        int p = wn*16 + nt*8 + tig*2;
                        *(float2*)&g_yd[dir][(base + l)*DI + h*64 + p] =
                            make_float2(f2[mt][nt][half*2], f2[mt][nt][half*2 + 1]);
                    }
                }
            }
        }

        // ---- phase 3: st[p][n] = sum_l dec[l]*XdtT[p][l]*BT[n][l] ----
        {
            float f3[2][2][4] = {};
            #pragma unroll
            for (int ks = 0; ks < 8; ks++) {
                int kb = ks*8;
                float d0 = sdec[kb + tig], d1 = sdec[kb + tig + 4];
                unsigned bf[2][2];
                #pragma unroll
                for (int nt = 0; nt < 2; nt++) {
                    int n = wn*16 + nt*8 + gid;
                    bf[nt][0] = __float_as_uint(sBT[n][kb + tig]);
                    bf[nt][1] = __float_as_uint(sBT[n][kb + tig + 4]);
                }
                #pragma unroll
                for (int mt = 0; mt < 2; mt++) {
                    int r = h*64 + wm*32 + mt*16 + gid;
                    unsigned a0 = __float_as_uint(f2tf32(sXT[r    ][kb + tig]     * d0));
                    unsigned a1 = __float_as_uint(f2tf32(sXT[r + 8][kb + tig]     * d0));
                    unsigned a2 = __float_as_uint(f2tf32(sXT[r    ][kb + tig + 4] * d1));
                    unsigned a3 = __float_as_uint(f2tf32(sXT[r + 8][kb + tig + 4] * d1));
                    mma_tf32(f3[mt][0], a0, a1, a2, a3, bf[0][0], bf[0][1]);
                    mma_tf32(f3[mt][1], a0, a1, a2, a3, bf[1][0], bf[1][1]);
                }
            }
            #pragma unroll
            for (int mt = 0; mt < 2; mt++) {
                #pragma unroll
                for (int half = 0; half < 2; half++) {
                    int p = wm*32 + mt*16 + gid + half*8;
                    #pragma unroll
                    for (int nt = 0; nt < 2; nt++) {
                        int n = wn*16 + nt*8 + tig*2;
                        *(float2*)&g_st[dir][sbase + h*4096 + p*64 + n] =
                            make_float2(f3[mt][nt][half*2], f3[mt][nt][half*2 + 1]);
                    }
                }
            }
        }
        if (tid == 0) g_cd[dir][(b*NH + h)*NC + c] = __expf(sAcs[h][63]);
    }
}

// ================= K4: inter-chunk scan — pipelined, vectorized ==============
__global__ __launch_bounds__(256) void k_scan()
{
    int grp = blockIdx.x;
    int bh  = blockIdx.y;
    int dir = blockIdx.z;
    int h = bh & 3, b = bh >> 2;
    int tid = threadIdx.x;
    int e0 = grp*1024 + tid*4;

    float cd[NC];
    #pragma unroll
    for (int c = 0; c < NC; c++) cd[c] = g_cd[dir][(b*NH + h)*NC + c];

    float* p = &g_st[dir][(b*NC*NH + h)*4096 + e0];
    const int cstride = NH*4096;

    float4 carry = make_float4(0.f, 0.f, 0.f, 0.f);
    float4 nxt = *(float4*)p;
    #pragma unroll
    for (int c = 0; c < NC; c++) {
        float4 cur = nxt;
        if (c + 1 < NC) nxt = *(float4*)(p + (c+1)*cstride);
        *(float4*)(p + c*cstride) = carry;
        float d = cd[c];
        carry.x = carry.x*d + cur.x;
        carry.y = carry.y*d + cur.y;
        carry.z = carry.z*d + cur.z;
        carry.w = carry.w*d + cur.w;
    }
}

// ================= K5: off-diag + gate + RMSnorm + out_proj via tf32 MMA =====
#define OUT_SMEM (39168*4)
__global__ __launch_bounds__(256) void k_out(
    const float* __restrict__ Al_f, const float* __restrict__ Al_b,
    const float* __restrict__ D_f,  const float* __restrict__ D_b,
    const float* __restrict__ nw_f, const float* __restrict__ nw_b,
    const float* __restrict__ Wo_f, const float* __restrict__ Wo_b,
    float* __restrict__ out)
{
    extern __shared__ float sm[];
    float (*sPrev)[68] = (float(*)[68])sm;            // [hp=256][n=64] tf32
    float (*sWo)[68]   = (float(*)[68])sm;            // alias
    float (*sY)[260]   = (float(*)[260])(sm + 17408);
    float (*sC)[68]    = (float(*)[68])(sm + 34048);
    float (*sdt)[4]    = (float(*)[4])(sm + 38400);
    float (*sAcs)[64]  = (float(*)[64])(sm + 38656);
    float (*sE)[64]    = (float(*)[64])(sm + 38912);

    int c = blockIdx.x, b = blockIdx.y;
    int tid = threadIdx.x;
    int wid = tid >> 5, lane = tid & 31;
    int gid = lane >> 2, tig = lane & 3;

    float oacc[8][4] = {};

    for (int d = 0; d < 2; d++) {
        int cc = d ? (NC - 1 - c) : c;
        int base = b*SEQL + cc*CH;
        const float* Alog = d ? Al_b : Al_f;
        const float* Dp   = d ? D_b  : D_f;
        const float* nw   = d ? nw_b : nw_f;
        const float* Wo   = d ? Wo_b : Wo_f;
        const float* gx   = g_xbc[d];

        __syncthreads();
        { int l = tid >> 2, h = tid & 3; sdt[l][h] = g_dt[d][base*NH + tid]; }
        __syncthreads();
        if (tid < 4) {
            float A = -__expf(Alog[tid]);
            float run = 0.f;
            for (int l = 0; l < 64; l++) { run += sdt[l][tid] * A; sAcs[tid][l] = run; }
        }
        __syncthreads();
        { int h = tid >> 6, l = tid & 63; sE[h][l] = __expf(sAcs[h][l]); }
        #pragma unroll
        for (int it = 0; it < 4; it++) {
            int q = tid + it*256;
            int row = q >> 4, nq = (q & 15) * 4;
            float4 v = *(const float4*)&gx[(base+row)*DX + DI + DS + nq];
            sC[row][nq+0] = f2tf32(v.x); sC[row][nq+1] = f2tf32(v.y);
            sC[row][nq+2] = f2tf32(v.z); sC[row][nq+3] = f2tf32(v.w);
        }
        {
            int pbase = (b*NC + cc)*NH*4096;
            #pragma unroll
            for (int it = 0; it < 16; it++) {
                int q = tid + it*256;
                int row = q >> 4, nq = (q & 15) * 4;
                float4 v = *(const float4*)&g_st[d][pbase + row*64 + nq];
                sPrev[row][nq+0] = f2tf32(v.x); sPrev[row][nq+1] = f2tf32(v.y);
                sPrev[row][nq+2] = f2tf32(v.z); sPrev[row][nq+3] = f2tf32(v.w);
            }
        }
        __syncthreads();

        {
            int wn = wid;
            float facc[4][4][4] = {};
            #pragma unroll
            for (int ks = 0; ks < 8; ks++) {
                int kb = ks*8;
                unsigned bf[4][2];
                #pragma unroll
                for (int nt = 0; nt < 4; nt++) {
                    int r = wn*32 + nt*8 + gid;
                    bf[nt][0] = __float_as_uint(sPrev[r][kb + tig]);
                    bf[nt][1] = __float_as_uint(sPrev[r][kb + tig + 4]);
                }
                #pragma unroll
                for (int mt = 0; mt < 4; mt++) {
                    int r = mt*16 + gid;
                    unsigned a0 = __float_as_uint(sC[r    ][kb + tig]);
                    unsigned a1 = __float_as_uint(sC[r + 8][kb + tig]);
                    unsigned a2 = __float_as_uint(sC[r    ][kb + tig + 4]);
                    unsigned a3 = __float_as_uint(sC[r + 8][kb + tig + 4]);
                    #pragma unroll
                    for (int nt = 0; nt < 4; nt++)
                        mma_tf32(facc[mt][nt], a0, a1, a2, a3, bf[nt][0], bf[nt][1]);
                }
            }
            #pragma unroll
            for (int mt = 0; mt < 4; mt++) {
                #pragma unroll
                for (int nt = 0; nt < 4; nt++) {
                    int q = wn*32 + nt*8 + tig*2;
                    int h = q >> 6;
                    float Dv = Dp[h];
                    #pragma unroll
                    for (int half = 0; half < 2; half++) {
                        int l = mt*16 + gid + half*8;
                        int row = base + l;
                        float e = sE[h][l];
                        float2 yd = *(const float2*)&g_yd[d][row*DI + q];
                        float2 xs = *(const float2*)&gx[row*DX + q];
                        float2 z2 = *(const float2*)&g_z[d][row*DI + q];
                        float v0 = facc[mt][nt][half*2 + 0];
                        float v1 = facc[mt][nt][half*2 + 1];
                        float y0 = (yd.x + e*v0 + Dv*xs.x) * siluf(z2.x);
                        float y1 = (yd.y + e*v1 + Dv*xs.y) * siluf(z2.y);
                        int srow = d ? (63 - l) : l;
                        *(float2*)&sY[srow][q] = make_float2(y0, y1);
                    }
                }
            }
        }
        __syncthreads();

        {
            int lr = tid >> 2, part = tid & 3;
            float s = 0.f;
            #pragma unroll
            for (int q = 0; q < 16; q++) {
                float4 v = *(float4*)&sY[lr][part*64 + q*4];
                s += dot4(v, v);
            }
            s += __shfl_xor_sync(0xffffffff, s, 1);
            s += __shfl_xor_sync(0xffffffff, s, 2);
            float scale = rsqrtf(s * (1.f/256.f) + 1e-5f);
            #pragma unroll
            for (int q = 0; q < 16; q++) {
                int col = part*64 + q*4;
                float4 v = *(float4*)&sY[lr][col];
                float4 w = *(const float4*)&nw[col];
                v.x = f2tf32(v.x * scale * w.x);
                v.y = f2tf32(v.y * scale * w.y);
                v.z = f2tf32(v.z * scale * w.z);
                v.w = f2tf32(v.w * scale * w.w);
                *(float4*)&sY[lr][col] = v;
            }
        }
        __syncthreads();

        {
            int wm = wid & 3, wn2 = wid >> 2;
            for (int jc = 0; jc < 4; jc++) {
                #pragma unroll
                for (int it = 0; it < 8; it++) {
                    int q = tid + it*256;
                    int row = q >> 4, jq = (q & 15) * 4;
                    float4 v = *(const float4*)&Wo[row*256 + jc*64 + jq];
                    sWo[row][jq+0] = f2tf32(v.x); sWo[row][jq+1] = f2tf32(v.y);
                    sWo[row][jq+2] = f2tf32(v.z); sWo[row][jq+3] = f2tf32(v.w);
                }
                __syncthreads();
                #pragma unroll
                for (int ks = 0; ks < 8; ks++) {
                    int kb = ks*8;
                    int ar = wm*16 + gid;
                    unsigned a0 = __float_as_uint(sY[ar    ][jc*64 + kb + tig]);
                    unsigned a1 = __float_as_uint(sY[ar + 8][jc*64 + kb + tig]);
                    unsigned a2 = __float_as_uint(sY[ar    ][jc*64 + kb + tig + 4]);
                    unsigned a3 = __float_as_uint(sY[ar + 8][jc*64 + kb + tig + 4]);
                    #pragma unroll
                    for (int nt = 0; nt < 8; nt++) {
                        int r = wn2*64 + nt*8 + gid;
                        unsigned b0 = __float_as_uint(sWo[r][kb + tig]);
                        unsigned b1 = __float_as_uint(sWo[r][kb + tig + 4]);
                        mma_tf32(oacc[nt], a0, a1, a2, a3, b0, b1);
                    }
                }
                __syncthreads();
            }
        }
    }

    {
        int wm = wid & 3, wn2 = wid >> 2;
        #pragma unroll
        for (int nt = 0; nt < 8; nt++) {
            int kout = wn2*64 + nt*8 + tig*2;
            #pragma unroll
            for (int half = 0; half < 2; half++) {
                int r = wm*16 + gid + half*8;
                int t = c*CH + r;
                *(float2*)&out[(b*SEQL + t)*DM + kout] =
                    make_float2(oacc[nt][half*2], oacc[nt][half*2 + 1]);
            }
        }
    }
}

extern "C" void kernel_launch(void* const* d_in, const int* in_sizes, int n_in,
                              void* d_out, int out_size)
{
    const float* x    = (const float*)d_in[0];
    const float* Wi_f = (const float*)d_in[1];
    const float* cw_f = (const float*)d_in[2];
    const float* cb_f = (const float*)d_in[3];
    const float* db_f = (const float*)d_in[4];
    const float* Al_f = (const float*)d_in[5];
    const float* D_f  = (const float*)d_in[6];
    const float* nw_f = (const float*)d_in[7];
    const float* Wo_f = (const float*)d_in[8];
    const float* Wi_b = (const float*)d_in[9];
    const float* cw_b = (const float*)d_in[10];
    const float* cb_b = (const float*)d_in[11];
    const float* db_b = (const float*)d_in[12];
    const float* Al_b = (const float*)d_in[13];
    const float* D_b  = (const float*)d_in[14];
    const float* nw_b = (const float*)d_in[15];
    const float* Wo_b = (const float*)d_in[16];
    float* out = (float*)d_out;

    cudaFuncSetAttribute(k_inproj, cudaFuncAttributeMaxDynamicSharedMemorySize, IP_SMEM);
    cudaFuncSetAttribute(k_chunk,  cudaFuncAttributeMaxDynamicSharedMemorySize, CH_SMEM);
    cudaFuncSetAttribute(k_out,    cudaFuncAttributeMaxDynamicSharedMemorySize, OUT_SMEM);

    dim3 g1(BL/128, (NPROJ + 63)/64, 2);
    k_inproj<<<g1, 256, IP_SMEM>>>(x, Wi_f, Wi_b, db_f, db_b);

    dim3 g2((BL*DX/4 + 255)/256, 2);
    k_conv<<<g2, 256>>>(cw_f, cb_f, cw_b, cb_b);

    dim3 g3(NC, BATCH, 2);
    k_chunk<<<g3, 256, CH_SMEM>>>(Al_f, Al_b);

    dim3 g4(4, BATCH*NH, 2);
    k_scan<<<g4, 256>>>();

    dim3 g5(NC, BATCH);
    k_out<<<g5, 256, OUT_SMEM>>>(Al_f, Al_b, D_f, D_b, nw_f, nw_b, Wo_f, Wo_b, out);
}